// round 6
// baseline (speedup 1.0000x reference)
#include <cuda_runtime.h>

#define NP 32768          // pixels = F*H*W = 2*128*128
#define SEQ 512           // window sequence length
#define NG 512            // head*window groups = 8*64

// ---------------- scratch (static __device__; no allocation APIs) ----------
__device__ float g_q [NG * SEQ * 64];          // [g][i][d]
__device__ float g_k [NG * SEQ * 64];          // [g][j][d]
__device__ float g_v [NG * SEQ * 64];          // [g][j][d]
__device__ float g_s [NG * SEQ * SEQ];         // [g][i][j]
__device__ float g_ow[NG * SEQ * 64];          // attn out, window layout
__device__ float g_op[512 * NP];               // attn out, pixel layout [ch][p]

// ---------------- tf32 helpers ---------------------------------------------
__device__ __forceinline__ float totf32(float x) {
    float r; asm("cvt.rna.tf32.f32 %0, %1;" : "=f"(r) : "f"(x)); return r;
}
__device__ __forceinline__ float2 splitf(float v) {
    float h = totf32(v);
    return make_float2(h, totf32(v - h));
}
// store one float4 as 4 (hi,lo) float2 pairs (two 16B stores)
__device__ __forceinline__ void sts_split4(float2* dst, float4 v) {
    float2 a = splitf(v.x), b = splitf(v.y), c = splitf(v.z), d = splitf(v.w);
    *(float4*)(dst)     = make_float4(a.x, a.y, b.x, b.y);
    *(float4*)(dst + 2) = make_float4(c.x, c.y, d.x, d.y);
}

__device__ __forceinline__ void mma_tf32(float* d, const unsigned* a, const unsigned* b) {
    asm("mma.sync.aligned.m16n8k8.row.col.f32.tf32.tf32.f32 "
        "{%0,%1,%2,%3}, {%4,%5,%6,%7}, {%8,%9}, {%0,%1,%2,%3};"
        : "+f"(d[0]), "+f"(d[1]), "+f"(d[2]), "+f"(d[3])
        : "r"(a[0]), "r"(a[1]), "r"(a[2]), "r"(a[3]), "r"(b[0]), "r"(b[1]));
}

// tf32x3 over one k=32 chunk (4 k8 steps), warp tile 64(M) x 32(N).
// SMEM holds (hi,lo) float2; fragments load via LDS.64. 3-pass MMA for ILP.
// AP/BP: float2* lane pointer expressions (use mt/nt, k0, g, tig, wm, wn).
// AO1: +8 rows of M (f2 units); AO2: +4 of K; BO1: +4 of K.
#define MMA3_K32_F2(AP, AO1, AO2, BP, BO1)                                    \
    _Pragma("unroll")                                                         \
    for (int ks = 0; ks < 4; ks++) {                                          \
        const int k0 = ks * 8;                                                \
        unsigned ah[4][4], al[4][4], bh[4][2], bl[4][2];                      \
        _Pragma("unroll")                                                     \
        for (int mt = 0; mt < 4; mt++) {                                      \
            const float2* _p = (AP);                                          \
            float2 f0 = _p[0], f1 = _p[(AO1)];                                \
            float2 f2 = _p[(AO2)], f3 = _p[(AO1) + (AO2)];                    \
            ah[mt][0] = __float_as_uint(f0.x); al[mt][0] = __float_as_uint(f0.y); \
            ah[mt][1] = __float_as_uint(f1.x); al[mt][1] = __float_as_uint(f1.y); \
            ah[mt][2] = __float_as_uint(f2.x); al[mt][2] = __float_as_uint(f2.y); \
            ah[mt][3] = __float_as_uint(f3.x); al[mt][3] = __float_as_uint(f3.y); \
        }                                                                     \
        _Pragma("unroll")                                                     \
        for (int nt = 0; nt < 4; nt++) {                                      \
            const float2* _q = (BP);                                          \
            float2 s0 = _q[0], s1 = _q[(BO1)];                                \
            bh[nt][0] = __float_as_uint(s0.x); bl[nt][0] = __float_as_uint(s0.y); \
            bh[nt][1] = __float_as_uint(s1.x); bl[nt][1] = __float_as_uint(s1.y); \
        }                                                                     \
        _Pragma("unroll")                                                     \
        for (int nt = 0; nt < 4; nt++)                                        \
            _Pragma("unroll")                                                 \
            for (int mt = 0; mt < 4; mt++)                                    \
                mma_tf32(acc[mt][nt], al[mt], bh[nt]);                        \
        _Pragma("unroll")                                                     \
        for (int nt = 0; nt < 4; nt++)                                        \
            _Pragma("unroll")                                                 \
            for (int mt = 0; mt < 4; mt++)                                    \
                mma_tf32(acc[mt][nt], ah[mt], bl[nt]);                        \
        _Pragma("unroll")                                                     \
        for (int nt = 0; nt < 4; nt++)                                        \
            _Pragma("unroll")                                                 \
            for (int mt = 0; mt < 4; mt++)                                    \
                mma_tf32(acc[mt][nt], ah[mt], bh[nt]);                        \
    }

#define ZERO_ACC()                                                            \
    float acc[4][4][4];                                                       \
    _Pragma("unroll")                                                         \
    for (int a = 0; a < 4; a++)                                               \
        _Pragma("unroll")                                                     \
        for (int b = 0; b < 4; b++)                                           \
            _Pragma("unroll")                                                 \
            for (int c = 0; c < 4; c++) acc[a][b][c] = 0.f;

// SMEM sizes (float2 elements)
#define PROJ_SMEM ((32 * 132 + 128 * 36) * 8)
#define QK_SMEM   ((128 * 36 * 2) * 8)
#define PV_SMEM   ((128 * 36 + 32 * 68) * 8)
#define OUT_SMEM  ((32 * 132 + 128 * 36) * 8)

// ============================================================================
// Kernel 1: QKV projection. out[o][p] = sum_c W[o][c] * x[c][p]
// Block 128p(M) x 128o(N), K chunks of 32. Xs [k][M] s132f2, Ws [N][k] s36f2.
// ============================================================================
__global__ void __launch_bounds__(256) proj_kernel(
    const float* __restrict__ x,
    const float* __restrict__ wq,
    const float* __restrict__ wkv)
{
    extern __shared__ __align__(16) float2 sm[];
    float2* Xs = sm;               // [32][132]
    float2* Ws = sm + 32 * 132;    // [128][36]

    const int tid  = threadIdx.x;
    const int lane = tid & 31, warp = tid >> 5;
    const int g = lane >> 2, tig = lane & 3;
    const int wm = (warp >> 2) * 64;       // p
    const int wn = (warp & 3) * 32;        // o
    const int p0 = blockIdx.x * 128;
    const int o0 = blockIdx.y * 128;

    ZERO_ACC();

    float4 xsr[4], wsr[4];
#define PROJ_LOAD(KT)                                                         \
    {                                                                         \
        const int c0 = (KT) * 32;                                             \
        _Pragma("unroll")                                                     \
        for (int q = 0; q < 4; q++) {                                         \
            int idx = q * 256 + tid;                                          \
            int xr = idx >> 5, xc = (idx & 31) * 4;                           \
            xsr[q] = *(const float4*)&x[(c0 + xr) * NP + p0 + xc];            \
            int orow = idx >> 3, cg = (idx & 7) * 4;                          \
            int o = o0 + orow;                                                \
            const float* arow = (o < 512) ? (wq + o * 256)                    \
                                          : (wkv + (o - 512) * 256);          \
            wsr[q] = *(const float4*)&arow[c0 + cg];                          \
        }                                                                     \
    }

    PROJ_LOAD(0)
    for (int kt = 0; kt < 8; kt++) {
        #pragma unroll
        for (int q = 0; q < 4; q++) {
            int idx = q * 256 + tid;
            int xr = idx >> 5, xc = (idx & 31) * 4;
            sts_split4(&Xs[xr * 132 + xc], xsr[q]);
            int orow = idx >> 3, cg = (idx & 7) * 4;
            sts_split4(&Ws[orow * 36 + cg], wsr[q]);
        }
        __syncthreads();
        if (kt < 7) PROJ_LOAD(kt + 1)
        MMA3_K32_F2(Xs + (k0 + tig) * 132 + wm + mt * 16 + g, 8, 528,
                    Ws + (wn + nt * 8 + g) * 36 + k0 + tig, 4);
        __syncthreads();
    }
#undef PROJ_LOAD

    // epilogue: D[m=p][n=o] fragments -> float2 along d into [g][i][d] bufs
    #pragma unroll
    for (int nt = 0; nt < 4; nt++) {
        int o   = o0 + wn + nt * 8 + 2 * tig;
        int sel = o >> 9;
        int oc  = o & 511;
        float* buf = (sel == 0) ? g_q : ((sel == 1) ? g_k : g_v);
        int gd = (oc >> 6) * 64;   // head*64
        int dl = oc & 63;
        #pragma unroll
        for (int mt = 0; mt < 4; mt++) {
            #pragma unroll
            for (int r = 0; r < 2; r++) {
                int p  = p0 + wm + mt * 16 + g + r * 8;
                int f  = p >> 14, hh = (p >> 7) & 127, ww = p & 127;
                int gidx = gd + (hh >> 4) * 8 + (ww >> 4);
                int i    = f * 256 + (hh & 15) * 16 + (ww & 15);
                *(float2*)&buf[(gidx * 512 + i) * 64 + dl] =
                    make_float2(acc[mt][nt][r * 2], acc[mt][nt][r * 2 + 1]);
            }
        }
    }
}

// ============================================================================
// Kernel 2: S = scale * Q @ K^T per group. Block 128i(M) x 128j(N), K=64.
// Qs [M][k] s36f2, Ks [N][k] s36f2.
// ============================================================================
__global__ void __launch_bounds__(256) qk_kernel()
{
    extern __shared__ __align__(16) float2 sm[];
    float2* Qs = sm;               // [128][36]
    float2* Ks = sm + 128 * 36;    // [128][36]

    const int tid  = threadIdx.x;
    const int lane = tid & 31, warp = tid >> 5;
    const int g = lane >> 2, tig = lane & 3;
    const int wm = (warp >> 2) * 64;       // i
    const int wn = (warp & 3) * 32;        // j
    const int gz = blockIdx.z;
    const int i0 = blockIdx.y * 128;
    const int j0 = blockIdx.x * 128;
    const float* qbase = g_q + gz * SEQ * 64;
    const float* kbase = g_k + gz * SEQ * 64;

    ZERO_ACC();

    float4 qsr[4], ksr[4];
#define QK_LOAD(DC)                                                           \
    {                                                                         \
        const int dc = (DC) * 32;                                             \
        _Pragma("unroll")                                                     \
        for (int q = 0; q < 4; q++) {                                         \
            int idx = q * 256 + tid;                                          \
            int row = idx >> 3, dg = (idx & 7) * 4;                           \
            qsr[q] = *(const float4*)&qbase[(i0 + row) * 64 + dc + dg];       \
            ksr[q] = *(const float4*)&kbase[(j0 + row) * 64 + dc + dg];       \
        }                                                                     \
    }

    QK_LOAD(0)
    for (int dcb = 0; dcb < 2; dcb++) {
        #pragma unroll
        for (int q = 0; q < 4; q++) {
            int idx = q * 256 + tid;
            int row = idx >> 3, dg = (idx & 7) * 4;
            sts_split4(&Qs[row * 36 + dg], qsr[q]);
            sts_split4(&Ks[row * 36 + dg], ksr[q]);
        }
        __syncthreads();
        if (dcb < 1) QK_LOAD(1)
        MMA3_K32_F2(Qs + (wm + mt * 16 + g) * 36 + k0 + tig, 288, 4,
                    Ks + (wn + nt * 8 + g) * 36 + k0 + tig, 4);
        __syncthreads();
    }
#undef QK_LOAD

    const float scale = 0.125f;
    #pragma unroll
    for (int mt = 0; mt < 4; mt++) {
        #pragma unroll
        for (int r = 0; r < 2; r++) {
            int i = i0 + wm + mt * 16 + g + r * 8;
            float* srow = &g_s[(gz * 512 + i) * 512 + j0];
            #pragma unroll
            for (int nt = 0; nt < 4; nt++) {
                int jj = wn + nt * 8 + 2 * tig;
                *(float2*)&srow[jj] = make_float2(acc[mt][nt][r * 2] * scale,
                                                  acc[mt][nt][r * 2 + 1] * scale);
            }
        }
    }
}

// ============================================================================
// Kernel 3: row softmax over j (512). One warp per row.
// ============================================================================
__global__ void __launch_bounds__(256) softmax_kernel()
{
    const int warp = threadIdx.x >> 5;
    const int lane = threadIdx.x & 31;
    const long long row = (long long)blockIdx.x * 8 + warp;
    float* rp = g_s + row * 512;

    float4 v[4];
    #pragma unroll
    for (int c = 0; c < 4; c++) v[c] = *(const float4*)&rp[c * 128 + lane * 4];

    float m = -1e30f;
    #pragma unroll
    for (int c = 0; c < 4; c++)
        m = fmaxf(m, fmaxf(fmaxf(v[c].x, v[c].y), fmaxf(v[c].z, v[c].w)));
    #pragma unroll
    for (int s = 16; s > 0; s >>= 1)
        m = fmaxf(m, __shfl_xor_sync(0xffffffffu, m, s));

    float sum = 0.f;
    #pragma unroll
    for (int c = 0; c < 4; c++) {
        v[c].x = __expf(v[c].x - m); v[c].y = __expf(v[c].y - m);
        v[c].z = __expf(v[c].z - m); v[c].w = __expf(v[c].w - m);
        sum += v[c].x + v[c].y + v[c].z + v[c].w;
    }
    #pragma unroll
    for (int s = 16; s > 0; s >>= 1)
        sum += __shfl_xor_sync(0xffffffffu, sum, s);

    const float inv = 1.0f / sum;
    #pragma unroll
    for (int c = 0; c < 4; c++) {
        v[c].x *= inv; v[c].y *= inv; v[c].z *= inv; v[c].w *= inv;
        *(float4*)&rp[c * 128 + lane * 4] = v[c];
    }
}

// ============================================================================
// Kernel 4: O = P @ V per group. Block 128i(M) x 64d(N), 128 threads.
// Ps [M][k] s36f2, Vs [k][N] s68f2. K = 512 in chunks of 32.
// ============================================================================
__global__ void __launch_bounds__(128, 3) pv_kernel()
{
    extern __shared__ __align__(16) float2 sm[];
    float2* Ps = sm;               // [128][36]
    float2* Vs = sm + 128 * 36;    // [32][68]

    const int tid  = threadIdx.x;
    const int lane = tid & 31, warp = tid >> 5;
    const int g = lane >> 2, tig = lane & 3;
    const int wm = (warp >> 1) * 64;       // i
    const int wn = (warp & 1) * 32;        // d
    const int gz = blockIdx.y;
    const int i0 = blockIdx.x * 128;
    const float* sbase = g_s + (long long)gz * 512 * 512;
    const float* vbase = g_v + gz * SEQ * 64;

    ZERO_ACC();

    float4 psr[8], vsr[4];
#define PV_LOAD(JT)                                                           \
    {                                                                         \
        const int j0 = (JT) * 32;                                             \
        _Pragma("unroll")                                                     \
        for (int q = 0; q < 8; q++) {                                         \
            int idx = q * 128 + tid;                                          \
            int row = idx >> 3, jg = (idx & 7) * 4;                           \
            psr[q] = *(const float4*)&sbase[(i0 + row) * 512 + j0 + jg];      \
        }                                                                     \
        _Pragma("unroll")                                                     \
        for (int q = 0; q < 4; q++) {                                         \
            int idx = q * 128 + tid;                                          \
            int vr = idx >> 4, vd = (idx & 15) * 4;                           \
            vsr[q] = *(const float4*)&vbase[(j0 + vr) * 64 + vd];             \
        }                                                                     \
    }

    PV_LOAD(0)
    for (int jt = 0; jt < 16; jt++) {
        #pragma unroll
        for (int q = 0; q < 8; q++) {
            int idx = q * 128 + tid;
            int row = idx >> 3, jg = (idx & 7) * 4;
            sts_split4(&Ps[row * 36 + jg], psr[q]);
        }
        #pragma unroll
        for (int q = 0; q < 4; q++) {
            int idx = q * 128 + tid;
            int vr = idx >> 4, vd = (idx & 15) * 4;
            sts_split4(&Vs[vr * 68 + vd], vsr[q]);
        }
        __syncthreads();
        if (jt < 15) PV_LOAD(jt + 1)
        MMA3_K32_F2(Ps + (wm + mt * 16 + g) * 36 + k0 + tig, 288, 4,
                    Vs + (k0 + tig) * 68 + wn + nt * 8 + g, 272);
        __syncthreads();
    }
#undef PV_LOAD

    #pragma unroll
    for (int mt = 0; mt < 4; mt++) {
        #pragma unroll
        for (int r = 0; r < 2; r++) {
            int i = i0 + wm + mt * 16 + g + r * 8;
            float* orow = &g_ow[(gz * 512 + i) * 64];
            #pragma unroll
            for (int nt = 0; nt < 4; nt++) {
                int d = wn + nt * 8 + 2 * tig;
                *(float2*)&orow[d] = make_float2(acc[mt][nt][r * 2],
                                                 acc[mt][nt][r * 2 + 1]);
            }
        }
    }
}

// ============================================================================
// Kernel 5: window layout [g][i][d] -> pixel layout [ch][p] via SMEM staging.
// ============================================================================
__global__ void __launch_bounds__(256) transpose_kernel()
{
    __shared__ __align__(16) float T[128][68];

    const int tid = threadIdx.x;
    const int g  = blockIdx.y;
    const int i0 = blockIdx.x * 128;
    const float* src = g_ow + (g * 512 + i0) * 64;

    #pragma unroll
    for (int q = 0; q < 8; q++) {
        int idx = q * 256 + tid;       // 0..2047
        int row = idx >> 4;            // 0..127
        int d4  = (idx & 15) * 4;
        *(float4*)&T[row][d4] = *(const float4*)&src[row * 64 + d4];
    }
    __syncthreads();

    const int head = g >> 6;
    const int win  = g & 63;
    const int wxv  = win >> 3, wyv = win & 7;

    #pragma unroll
    for (int q = 0; q < 2; q++) {
        int t   = q * 256 + tid;       // 0..511
        int d   = t & 63;
        int run = t >> 6;              // 0..7
        int ib  = run * 16;
        int ig  = i0 + ib;
        int f   = ig >> 8;
        int w1  = (ig >> 4) & 15;
        int pbase = f * 16384 + (wxv * 16 + w1) * 128 + wyv * 16;
        float* dst = g_op + (head * 64 + d) * NP + pbase;
        #pragma unroll
        for (int e = 0; e < 4; e++) {
            float4 v4;
            v4.x = T[ib + e * 4 + 0][d];
            v4.y = T[ib + e * 4 + 1][d];
            v4.z = T[ib + e * 4 + 2][d];
            v4.w = T[ib + e * 4 + 3][d];
            *(float4*)&dst[e * 4] = v4;
        }
    }
}

// ============================================================================
// Kernel 6: final projection + bias. Block 128o(M) x 128p(N), K=512.
// Ws [M][k] s36f2, Bs [k][N] s132f2. Stores coalesced along p.
// ============================================================================
__global__ void __launch_bounds__(256) out_kernel(
    const float* __restrict__ wo,
    const float* __restrict__ bo,
    float* __restrict__ out)
{
    extern __shared__ __align__(16) float2 sm[];
    float2* Bs = sm;               // [32][132]
    float2* Ws = sm + 32 * 132;    // [128][36]

    const int tid  = threadIdx.x;
    const int lane = tid & 31, warp = tid >> 5;
    const int g = lane >> 2, tig = lane & 3;
    const int wm = (warp >> 2) * 64;       // o
    const int wn = (warp & 3) * 32;        // p
    const int p0 = blockIdx.x * 128;
    const int o0 = blockIdx.y * 128;

    ZERO_ACC();

    float4 bsr[4], wsr[4];
#define OUT_LOAD(KT)                                                          \
    {                                                                         \
        const int c0 = (KT) * 32;                                             \
        _Pragma("unroll")                                                     \
        for (int q = 0; q < 4; q++) {                                         \
            int idx = q * 256 + tid;                                          \
            int xr = idx >> 5, xc = (idx & 31) * 4;                           \
            bsr[q] = *(const float4*)&g_op[(c0 + xr) * NP + p0 + xc];         \
            int orow = idx >> 3, cg = (idx & 7) * 4;                          \
            wsr[q] = *(const float4*)&wo[(o0 + orow) * 512 + c0 + cg];        \
        }                                                                     \
    }

    OUT_LOAD(0)
    for (int kt = 0; kt < 16; kt++) {
        #pragma unroll
        for (int q = 0; q < 4; q++) {
            int idx = q * 256 + tid;
            int xr = idx >> 5, xc = (idx & 31) * 4;
            sts_split4(&Bs[xr * 132 + xc], bsr[q]);
            int orow = idx >> 3, cg = (idx & 7) * 4;
            sts_split4(&Ws[orow * 36 + cg], wsr[q]);
        }
        __syncthreads();
        if (kt < 15) OUT_LOAD(kt + 1)
        MMA3_K32_F2(Ws + (wm + mt * 16 + g) * 36 + k0 + tig, 288, 4,
                    Bs + (k0 + tig) * 132 + wn + nt * 8 + g, 528);
        __syncthreads();
    }
#undef OUT_LOAD

    #pragma unroll
    for (int mt = 0; mt < 4; mt++) {
        int o  = o0 + wm + mt * 16 + g;
        float b0 = bo[o];
        float b1 = bo[o + 8];
        #pragma unroll
        for (int nt = 0; nt < 4; nt++) {
            int p = p0 + wn + nt * 8 + 2 * tig;
            *(float2*)&out[o * NP + p] =
                make_float2(acc[mt][nt][0] + b0, acc[mt][nt][1] + b0);
            *(float2*)&out[(o + 8) * NP + p] =
                make_float2(acc[mt][nt][2] + b1, acc[mt][nt][3] + b1);
        }
    }
}

// ============================================================================
extern "C" void kernel_launch(void* const* d_in, const int* in_sizes, int n_in,
                              void* d_out, int out_size)
{
    const float* x   = (const float*)d_in[0];
    const float* wq  = (const float*)d_in[1];
    const float* wkv = (const float*)d_in[2];
    const float* wo  = (const float*)d_in[3];
    const float* bo  = (const float*)d_in[4];
    float* out = (float*)d_out;

    static int attr_done = 0;
    if (!attr_done) {
        cudaFuncSetAttribute(proj_kernel, cudaFuncAttributeMaxDynamicSharedMemorySize, PROJ_SMEM);
        cudaFuncSetAttribute(qk_kernel,   cudaFuncAttributeMaxDynamicSharedMemorySize, QK_SMEM);
        cudaFuncSetAttribute(pv_kernel,   cudaFuncAttributeMaxDynamicSharedMemorySize, PV_SMEM);
        cudaFuncSetAttribute(out_kernel,  cudaFuncAttributeMaxDynamicSharedMemorySize, OUT_SMEM);
        attr_done = 1;
    }

    proj_kernel     <<<dim3(NP / 128, 1536 / 128), 256, PROJ_SMEM>>>(x, wq, wkv);
    qk_kernel       <<<dim3(4, 4, NG),             256, QK_SMEM>>>();
    softmax_kernel  <<<dim3(NG * SEQ / 8),         256>>>();
    pv_kernel       <<<dim3(4, NG),                128, PV_SMEM>>>();
    transpose_kernel<<<dim3(4, NG),                256>>>();
    out_kernel      <<<dim3(NP / 128, 256 / 128),  256, OUT_SMEM>>>(wo, bo, out);
}

// round 7
// speedup vs baseline: 1.6038x; 1.6038x over previous
#include <cuda_runtime.h>
#include <cuda_fp16.h>

#define NP 32768          // pixels = F*H*W = 2*128*128
#define SEQ 512           // window sequence length
#define NG 512            // head*window groups = 8*64

// ---------------- scratch (static __device__; no allocation APIs) ----------
__device__ float g_q [NG * SEQ * 64];          // [g][i][d]
__device__ float g_k [NG * SEQ * 64];          // [g][j][d]
__device__ float g_v [NG * SEQ * 64];          // [g][j][d]
__device__ float g_s [NG * SEQ * SEQ];         // [g][i][j]
__device__ float g_ow[NG * SEQ * 64];          // attn out, window layout
__device__ float g_op[512 * NP];               // attn out, pixel layout [ch][p]

// ---------------- fp16x2 split helpers --------------------------------------
// pack two floats as half2 word (a in low = even k, b in high = odd k)
__device__ __forceinline__ unsigned pk(float a, float b) {
    return (unsigned)__half_as_ushort(__float2half_rn(a)) |
           ((unsigned)__half_as_ushort(__float2half_rn(b)) << 16);
}
// split (a,b) into hi-plane word and lo-plane (residual) word
__device__ __forceinline__ void split_pack(float a, float b, unsigned& hi, unsigned& lo) {
    __half ha = __float2half_rn(a), hb = __float2half_rn(b);
    hi = (unsigned)__half_as_ushort(ha) | ((unsigned)__half_as_ushort(hb) << 16);
    lo = pk(a - __half2float(ha), b - __half2float(hb));
}

__device__ __forceinline__ void mma_f16(float* d, const unsigned* a, const unsigned* b) {
    asm("mma.sync.aligned.m16n8k16.row.col.f32.f16.f16.f32 "
        "{%0,%1,%2,%3}, {%4,%5,%6,%7}, {%8,%9}, {%0,%1,%2,%3};"
        : "+f"(d[0]), "+f"(d[1]), "+f"(d[2]), "+f"(d[3])
        : "r"(a[0]), "r"(a[1]), "r"(a[2]), "r"(a[3]), "r"(b[0]), "r"(b[1]));
}

// fp16x2 3-term over one k=32 (real) chunk = 2 m16n8k16 steps.
// SMEM planes hold packed half2 words (k-pairs). Warp tile 64(M) x 32(N).
// APH/APL/BPH/BPL: lane word-pointer expressions (use mt/nt, k2w, g, tig, wm, wn).
// AOR: +8 rows of M (words); AOK: +4 k-pairs; BOK: +4 k-pairs.
#define MMAH_K32(APH, APL, AOR, AOK, BPH, BPL, BOK)                           \
    _Pragma("unroll")                                                        \
    for (int ks = 0; ks < 2; ks++) {                                         \
        const int k2w = ks * 8 + tig;                                        \
        unsigned ah[4][4], al[4][4], bh[4][2], bl[4][2];                     \
        _Pragma("unroll")                                                    \
        for (int mt = 0; mt < 4; mt++) {                                     \
            const unsigned* _ph = (APH);                                     \
            const unsigned* _pl = (APL);                                     \
            ah[mt][0] = _ph[0];            al[mt][0] = _pl[0];               \
            ah[mt][1] = _ph[(AOR)];        al[mt][1] = _pl[(AOR)];           \
            ah[mt][2] = _ph[(AOK)];        al[mt][2] = _pl[(AOK)];           \
            ah[mt][3] = _ph[(AOR)+(AOK)];  al[mt][3] = _pl[(AOR)+(AOK)];     \
        }                                                                    \
        _Pragma("unroll")                                                    \
        for (int nt = 0; nt < 4; nt++) {                                     \
            const unsigned* _qh = (BPH);                                     \
            const unsigned* _ql = (BPL);                                     \
            bh[nt][0] = _qh[0];  bh[nt][1] = _qh[(BOK)];                     \
            bl[nt][0] = _ql[0];  bl[nt][1] = _ql[(BOK)];                     \
        }                                                                    \
        _Pragma("unroll")                                                    \
        for (int nt = 0; nt < 4; nt++)                                       \
            _Pragma("unroll")                                                \
            for (int mt = 0; mt < 4; mt++)                                   \
                mma_f16(acc[mt][nt], al[mt], bh[nt]);                        \
        _Pragma("unroll")                                                    \
        for (int nt = 0; nt < 4; nt++)                                       \
            _Pragma("unroll")                                                \
            for (int mt = 0; mt < 4; mt++)                                   \
                mma_f16(acc[mt][nt], ah[mt], bl[nt]);                        \
        _Pragma("unroll")                                                    \
        for (int nt = 0; nt < 4; nt++)                                       \
            _Pragma("unroll")                                                \
            for (int mt = 0; mt < 4; mt++)                                   \
                mma_f16(acc[mt][nt], ah[mt], bh[nt]);                        \
    }

#define ZERO_ACC()                                                            \
    float acc[4][4][4];                                                       \
    _Pragma("unroll")                                                         \
    for (int a = 0; a < 4; a++)                                               \
        _Pragma("unroll")                                                     \
        for (int b = 0; b < 4; b++)                                           \
            _Pragma("unroll")                                                 \
            for (int c = 0; c < 4; c++) acc[a][b][c] = 0.f;

// ============================================================================
// Kernel 1: QKV projection. out[o][p] = sum_c W[o][c] * x[c][p]
// Block 128p(M) x 128o(N), K chunks of 32.
// Xs planes [c2=16][136 p-words], Ws planes [128 o][20 c2-words].
// ============================================================================
__global__ void __launch_bounds__(256) proj_kernel(
    const float* __restrict__ x,
    const float* __restrict__ wq,
    const float* __restrict__ wkv)
{
    __shared__ __align__(16) unsigned XsH[16 * 136], XsL[16 * 136];
    __shared__ __align__(16) unsigned WsH[128 * 20], WsL[128 * 20];

    const int tid  = threadIdx.x;
    const int lane = tid & 31, warp = tid >> 5;
    const int g = lane >> 2, tig = lane & 3;
    const int wm = (warp >> 2) * 64;       // p
    const int wn = (warp & 3) * 32;        // o
    const int p0 = blockIdx.x * 128;
    const int o0 = blockIdx.y * 128;

    ZERO_ACC();

    for (int kt = 0; kt < 8; kt++) {
        const int c0 = kt * 32;
        #pragma unroll
        for (int q = 0; q < 2; q++) {
            int idx = q * 256 + tid;              // 0..511
            // Xs: pack 2 c-rows per p
            int c2 = idx >> 5, pc = (idx & 31) * 4;
            float4 r0 = *(const float4*)&x[(c0 + 2 * c2)     * NP + p0 + pc];
            float4 r1 = *(const float4*)&x[(c0 + 2 * c2 + 1) * NP + p0 + pc];
            unsigned h0,l0,h1,l1,h2,l2,h3,l3;
            split_pack(r0.x, r1.x, h0, l0); split_pack(r0.y, r1.y, h1, l1);
            split_pack(r0.z, r1.z, h2, l2); split_pack(r0.w, r1.w, h3, l3);
            *(uint4*)&XsH[c2 * 136 + pc] = make_uint4(h0, h1, h2, h3);
            *(uint4*)&XsL[c2 * 136 + pc] = make_uint4(l0, l1, l2, l3);
            // Ws: pack along c (8 consecutive c = 4 words)
            int orow = idx >> 2, cg = (idx & 3) * 8;
            int o = o0 + orow;
            const float* arow = (o < 512) ? (wq + o * 256) : (wkv + (o - 512) * 256);
            float4 w0 = *(const float4*)&arow[c0 + cg];
            float4 w1 = *(const float4*)&arow[c0 + cg + 4];
            split_pack(w0.x, w0.y, h0, l0); split_pack(w0.z, w0.w, h1, l1);
            split_pack(w1.x, w1.y, h2, l2); split_pack(w1.z, w1.w, h3, l3);
            *(uint4*)&WsH[orow * 20 + cg / 2] = make_uint4(h0, h1, h2, h3);
            *(uint4*)&WsL[orow * 20 + cg / 2] = make_uint4(l0, l1, l2, l3);
        }
        __syncthreads();
        MMAH_K32(&XsH[k2w * 136 + wm + mt * 16 + g],
                 &XsL[k2w * 136 + wm + mt * 16 + g], 8, 544,
                 &WsH[(wn + nt * 8 + g) * 20 + k2w],
                 &WsL[(wn + nt * 8 + g) * 20 + k2w], 4);
        __syncthreads();
    }

    // epilogue: D[m=p][n=o] fragments -> float2 along d into [g][i][d] bufs
    #pragma unroll
    for (int nt = 0; nt < 4; nt++) {
        int o   = o0 + wn + nt * 8 + 2 * tig;
        int sel = o >> 9;
        int oc  = o & 511;
        float* buf = (sel == 0) ? g_q : ((sel == 1) ? g_k : g_v);
        int gd = (oc >> 6) * 64;   // head*64
        int dl = oc & 63;
        #pragma unroll
        for (int mt = 0; mt < 4; mt++) {
            #pragma unroll
            for (int r = 0; r < 2; r++) {
                int p  = p0 + wm + mt * 16 + g + r * 8;
                int f  = p >> 14, hh = (p >> 7) & 127, ww = p & 127;
                int gidx = gd + (hh >> 4) * 8 + (ww >> 4);
                int i    = f * 256 + (hh & 15) * 16 + (ww & 15);
                *(float2*)&buf[(gidx * 512 + i) * 64 + dl] =
                    make_float2(acc[mt][nt][r * 2], acc[mt][nt][r * 2 + 1]);
            }
        }
    }
}

// ============================================================================
// Kernel 2: S = scale * Q @ K^T per group. Block 128i(M) x 128j(N), K=64.
// Qs/Ks planes [128][20] (k packed along d).
// ============================================================================
__global__ void __launch_bounds__(256) qk_kernel()
{
    __shared__ __align__(16) unsigned QsH[128 * 20], QsL[128 * 20];
    __shared__ __align__(16) unsigned KsH[128 * 20], KsL[128 * 20];

    const int tid  = threadIdx.x;
    const int lane = tid & 31, warp = tid >> 5;
    const int g = lane >> 2, tig = lane & 3;
    const int wm = (warp >> 2) * 64;       // i
    const int wn = (warp & 3) * 32;        // j
    const int gz = blockIdx.z;
    const int i0 = blockIdx.y * 128;
    const int j0 = blockIdx.x * 128;
    const float* qbase = g_q + gz * SEQ * 64;
    const float* kbase = g_k + gz * SEQ * 64;

    ZERO_ACC();

    for (int dcb = 0; dcb < 2; dcb++) {
        const int dc = dcb * 32;
        #pragma unroll
        for (int q = 0; q < 2; q++) {
            int idx = q * 256 + tid;              // 0..511
            int row = idx >> 2, dg = (idx & 3) * 8;
            unsigned h0,l0,h1,l1,h2,l2,h3,l3;
            float4 q0 = *(const float4*)&qbase[(i0 + row) * 64 + dc + dg];
            float4 q1 = *(const float4*)&qbase[(i0 + row) * 64 + dc + dg + 4];
            split_pack(q0.x, q0.y, h0, l0); split_pack(q0.z, q0.w, h1, l1);
            split_pack(q1.x, q1.y, h2, l2); split_pack(q1.z, q1.w, h3, l3);
            *(uint4*)&QsH[row * 20 + dg / 2] = make_uint4(h0, h1, h2, h3);
            *(uint4*)&QsL[row * 20 + dg / 2] = make_uint4(l0, l1, l2, l3);
            float4 k0v = *(const float4*)&kbase[(j0 + row) * 64 + dc + dg];
            float4 k1v = *(const float4*)&kbase[(j0 + row) * 64 + dc + dg + 4];
            split_pack(k0v.x, k0v.y, h0, l0); split_pack(k0v.z, k0v.w, h1, l1);
            split_pack(k1v.x, k1v.y, h2, l2); split_pack(k1v.z, k1v.w, h3, l3);
            *(uint4*)&KsH[row * 20 + dg / 2] = make_uint4(h0, h1, h2, h3);
            *(uint4*)&KsL[row * 20 + dg / 2] = make_uint4(l0, l1, l2, l3);
        }
        __syncthreads();
        MMAH_K32(&QsH[(wm + mt * 16 + g) * 20 + k2w],
                 &QsL[(wm + mt * 16 + g) * 20 + k2w], 160, 4,
                 &KsH[(wn + nt * 8 + g) * 20 + k2w],
                 &KsL[(wn + nt * 8 + g) * 20 + k2w], 4);
        __syncthreads();
    }

    const float scale = 0.125f;
    #pragma unroll
    for (int mt = 0; mt < 4; mt++) {
        #pragma unroll
        for (int r = 0; r < 2; r++) {
            int i = i0 + wm + mt * 16 + g + r * 8;
            float* srow = &g_s[(gz * 512 + i) * 512 + j0];
            #pragma unroll
            for (int nt = 0; nt < 4; nt++) {
                int jj = wn + nt * 8 + 2 * tig;
                *(float2*)&srow[jj] = make_float2(acc[mt][nt][r * 2] * scale,
                                                  acc[mt][nt][r * 2 + 1] * scale);
            }
        }
    }
}

// ============================================================================
// Kernel 3: row softmax over j (512). One warp per row.
// ============================================================================
__global__ void __launch_bounds__(256) softmax_kernel()
{
    const int warp = threadIdx.x >> 5;
    const int lane = threadIdx.x & 31;
    const long long row = (long long)blockIdx.x * 8 + warp;
    float* rp = g_s + row * 512;

    float4 v[4];
    #pragma unroll
    for (int c = 0; c < 4; c++) v[c] = *(const float4*)&rp[c * 128 + lane * 4];

    float m = -1e30f;
    #pragma unroll
    for (int c = 0; c < 4; c++)
        m = fmaxf(m, fmaxf(fmaxf(v[c].x, v[c].y), fmaxf(v[c].z, v[c].w)));
    #pragma unroll
    for (int s = 16; s > 0; s >>= 1)
        m = fmaxf(m, __shfl_xor_sync(0xffffffffu, m, s));

    float sum = 0.f;
    #pragma unroll
    for (int c = 0; c < 4; c++) {
        v[c].x = __expf(v[c].x - m); v[c].y = __expf(v[c].y - m);
        v[c].z = __expf(v[c].z - m); v[c].w = __expf(v[c].w - m);
        sum += v[c].x + v[c].y + v[c].z + v[c].w;
    }
    #pragma unroll
    for (int s = 16; s > 0; s >>= 1)
        sum += __shfl_xor_sync(0xffffffffu, sum, s);

    const float inv = 1.0f / sum;
    #pragma unroll
    for (int c = 0; c < 4; c++) {
        v[c].x *= inv; v[c].y *= inv; v[c].z *= inv; v[c].w *= inv;
        *(float4*)&rp[c * 128 + lane * 4] = v[c];
    }
}

// ============================================================================
// Kernel 4: O = P @ V per group. Block 128i(M) x 64d(N), 128 threads.
// Ps planes [128][20] (k=j packed); Vs planes [j2=16][72 d-words].
// ============================================================================
__global__ void __launch_bounds__(128) pv_kernel()
{
    __shared__ __align__(16) unsigned PsH[128 * 20], PsL[128 * 20];
    __shared__ __align__(16) unsigned VsH[16 * 72],  VsL[16 * 72];

    const int tid  = threadIdx.x;
    const int lane = tid & 31, warp = tid >> 5;
    const int g = lane >> 2, tig = lane & 3;
    const int wm = (warp >> 1) * 64;       // i
    const int wn = (warp & 1) * 32;        // d
    const int gz = blockIdx.y;
    const int i0 = blockIdx.x * 128;
    const float* sbase = g_s + (long long)gz * 512 * 512;
    const float* vbase = g_v + gz * SEQ * 64;

    ZERO_ACC();

    for (int jt = 0; jt < 16; jt++) {
        const int j0 = jt * 32;
        #pragma unroll
        for (int q = 0; q < 4; q++) {
            int idx = q * 128 + tid;              // 0..511
            int row = idx >> 2, jg = (idx & 3) * 8;
            float4 r0 = *(const float4*)&sbase[(i0 + row) * 512 + j0 + jg];
            float4 r1 = *(const float4*)&sbase[(i0 + row) * 512 + j0 + jg + 4];
            unsigned h0,l0,h1,l1,h2,l2,h3,l3;
            split_pack(r0.x, r0.y, h0, l0); split_pack(r0.z, r0.w, h1, l1);
            split_pack(r1.x, r1.y, h2, l2); split_pack(r1.z, r1.w, h3, l3);
            *(uint4*)&PsH[row * 20 + jg / 2] = make_uint4(h0, h1, h2, h3);
            *(uint4*)&PsL[row * 20 + jg / 2] = make_uint4(l0, l1, l2, l3);
        }
        #pragma unroll
        for (int q = 0; q < 2; q++) {
            int idx = q * 128 + tid;              // 0..255
            int jr = idx >> 4, dq = (idx & 15) * 4;
            float4 r0 = *(const float4*)&vbase[(j0 + 2 * jr)     * 64 + dq];
            float4 r1 = *(const float4*)&vbase[(j0 + 2 * jr + 1) * 64 + dq];
            unsigned h0,l0,h1,l1,h2,l2,h3,l3;
            split_pack(r0.x, r1.x, h0, l0); split_pack(r0.y, r1.y, h1, l1);
            split_pack(r0.z, r1.z, h2, l2); split_pack(r0.w, r1.w, h3, l3);
            *(uint4*)&VsH[jr * 72 + dq] = make_uint4(h0, h1, h2, h3);
            *(uint4*)&VsL[jr * 72 + dq] = make_uint4(l0, l1, l2, l3);
        }
        __syncthreads();
        MMAH_K32(&PsH[(wm + mt * 16 + g) * 20 + k2w],
                 &PsL[(wm + mt * 16 + g) * 20 + k2w], 160, 4,
                 &VsH[k2w * 72 + wn + nt * 8 + g],
                 &VsL[k2w * 72 + wn + nt * 8 + g], 288);
        __syncthreads();
    }

    #pragma unroll
    for (int mt = 0; mt < 4; mt++) {
        #pragma unroll
        for (int r = 0; r < 2; r++) {
            int i = i0 + wm + mt * 16 + g + r * 8;
            float* orow = &g_ow[(gz * 512 + i) * 64];
            #pragma unroll
            for (int nt = 0; nt < 4; nt++) {
                int d = wn + nt * 8 + 2 * tig;
                *(float2*)&orow[d] = make_float2(acc[mt][nt][r * 2],
                                                 acc[mt][nt][r * 2 + 1]);
            }
        }
    }
}

// ============================================================================
// Kernel 5: window layout [g][i][d] -> pixel layout [ch][p] via SMEM staging.
// ============================================================================
__global__ void __launch_bounds__(256) transpose_kernel()
{
    __shared__ __align__(16) float T[128][68];

    const int tid = threadIdx.x;
    const int g  = blockIdx.y;
    const int i0 = blockIdx.x * 128;
    const float* src = g_ow + (g * 512 + i0) * 64;

    #pragma unroll
    for (int q = 0; q < 8; q++) {
        int idx = q * 256 + tid;       // 0..2047
        int row = idx >> 4;            // 0..127
        int d4  = (idx & 15) * 4;
        *(float4*)&T[row][d4] = *(const float4*)&src[row * 64 + d4];
    }
    __syncthreads();

    const int head = g >> 6;
    const int win  = g & 63;
    const int wxv  = win >> 3, wyv = win & 7;

    #pragma unroll
    for (int q = 0; q < 2; q++) {
        int t   = q * 256 + tid;       // 0..511
        int d   = t & 63;
        int run = t >> 6;              // 0..7
        int ib  = run * 16;
        int ig  = i0 + ib;
        int f   = ig >> 8;
        int w1  = (ig >> 4) & 15;
        int pbase = f * 16384 + (wxv * 16 + w1) * 128 + wyv * 16;
        float* dst = g_op + (head * 64 + d) * NP + pbase;
        #pragma unroll
        for (int e = 0; e < 4; e++) {
            float4 v4;
            v4.x = T[ib + e * 4 + 0][d];
            v4.y = T[ib + e * 4 + 1][d];
            v4.z = T[ib + e * 4 + 2][d];
            v4.w = T[ib + e * 4 + 3][d];
            *(float4*)&dst[e * 4] = v4;
        }
    }
}

// ============================================================================
// Kernel 6: final projection + bias. Block 128o(M) x 128p(N), K=512.
// Ws planes [128 o][20]; Bs planes [c2=16][136 p-words].
// ============================================================================
__global__ void __launch_bounds__(256) out_kernel(
    const float* __restrict__ wo,
    const float* __restrict__ bo,
    float* __restrict__ out)
{
    __shared__ __align__(16) unsigned BsH[16 * 136], BsL[16 * 136];
    __shared__ __align__(16) unsigned WsH[128 * 20], WsL[128 * 20];

    const int tid  = threadIdx.x;
    const int lane = tid & 31, warp = tid >> 5;
    const int g = lane >> 2, tig = lane & 3;
    const int wm = (warp >> 2) * 64;       // o
    const int wn = (warp & 3) * 32;        // p
    const int p0 = blockIdx.x * 128;
    const int o0 = blockIdx.y * 128;

    ZERO_ACC();

    for (int kt = 0; kt < 16; kt++) {
        const int c0 = kt * 32;
        #pragma unroll
        for (int q = 0; q < 2; q++) {
            int idx = q * 256 + tid;
            int c2 = idx >> 5, pc = (idx & 31) * 4;
            float4 r0 = *(const float4*)&g_op[(c0 + 2 * c2)     * NP + p0 + pc];
            float4 r1 = *(const float4*)&g_op[(c0 + 2 * c2 + 1) * NP + p0 + pc];
            unsigned h0,l0,h1,l1,h2,l2,h3,l3;
            split_pack(r0.x, r1.x, h0, l0); split_pack(r0.y, r1.y, h1, l1);
            split_pack(r0.z, r1.z, h2, l2); split_pack(r0.w, r1.w, h3, l3);
            *(uint4*)&BsH[c2 * 136 + pc] = make_uint4(h0, h1, h2, h3);
            *(uint4*)&BsL[c2 * 136 + pc] = make_uint4(l0, l1, l2, l3);
            int orow = idx >> 2, cg = (idx & 3) * 8;
            float4 w0 = *(const float4*)&wo[(o0 + orow) * 512 + c0 + cg];
            float4 w1 = *(const float4*)&wo[(o0 + orow) * 512 + c0 + cg + 4];
            split_pack(w0.x, w0.y, h0, l0); split_pack(w0.z, w0.w, h1, l1);
            split_pack(w1.x, w1.y, h2, l2); split_pack(w1.z, w1.w, h3, l3);
            *(uint4*)&WsH[orow * 20 + cg / 2] = make_uint4(h0, h1, h2, h3);
            *(uint4*)&WsL[orow * 20 + cg / 2] = make_uint4(l0, l1, l2, l3);
        }
        __syncthreads();
        MMAH_K32(&WsH[(wm + mt * 16 + g) * 20 + k2w],
                 &WsL[(wm + mt * 16 + g) * 20 + k2w], 160, 4,
                 &BsH[k2w * 136 + wn + nt * 8 + g],
                 &BsL[k2w * 136 + wn + nt * 8 + g], 544);
        __syncthreads();
    }

    #pragma unroll
    for (int mt = 0; mt < 4; mt++) {
        int o  = o0 + wm + mt * 16 + g;
        float b0 = bo[o];
        float b1 = bo[o + 8];
        #pragma unroll
        for (int nt = 0; nt < 4; nt++) {
            int p = p0 + wn + nt * 8 + 2 * tig;
            *(float2*)&out[o * NP + p] =
                make_float2(acc[mt][nt][0] + b0, acc[mt][nt][1] + b0);
            *(float2*)&out[(o + 8) * NP + p] =
                make_float2(acc[mt][nt][2] + b1, acc[mt][nt][3] + b1);
        }
    }
}

// ============================================================================
extern "C" void kernel_launch(void* const* d_in, const int* in_sizes, int n_in,
                              void* d_out, int out_size)
{
    const float* x   = (const float*)d_in[0];
    const float* wq  = (const float*)d_in[1];
    const float* wkv = (const float*)d_in[2];
    const float* wo  = (const float*)d_in[3];
    const float* bo  = (const float*)d_in[4];
    float* out = (float*)d_out;

    proj_kernel     <<<dim3(NP / 128, 1536 / 128), 256>>>(x, wq, wkv);
    qk_kernel       <<<dim3(4, 4, NG),             256>>>();
    softmax_kernel  <<<dim3(NG * SEQ / 8),         256>>>();
    pv_kernel       <<<dim3(4, NG),                128>>>();
    transpose_kernel<<<dim3(4, NG),                256>>>();
    out_kernel      <<<dim3(NP / 128, 256 / 128),  256>>>(wo, bo, out);
}

// round 8
// speedup vs baseline: 2.0081x; 1.2521x over previous
#include <cuda_runtime.h>
#include <cuda_fp16.h>

#define NP 32768          // pixels = F*H*W = 2*128*128
#define SEQ 512           // window sequence length
#define NG 512            // head*window groups = 8*64

// ---------------- scratch (static __device__; no allocation APIs) ----------
// Q/K planes: [g][i][32 d-pair words], hi & lo
__device__ unsigned g_qh[NG * SEQ * 32], g_ql[NG * SEQ * 32];
__device__ unsigned g_kh[NG * SEQ * 32], g_kl[NG * SEQ * 32];
// V planes: [g][j2][64 d words] (j-pairs packed per word)
__device__ unsigned g_vh[NG * 256 * 64], g_vl[NG * 256 * 64];
// S (fp32, qk out -> softmax in)
__device__ float    g_s [NG * SEQ * SEQ];
// P planes: [g][i][256 j-pair words]
__device__ unsigned g_ph[NG * SEQ * 256], g_pl[NG * SEQ * 256];
__device__ float    g_ow[NG * SEQ * 64];   // attn out, window layout
__device__ float    g_op[512 * NP];        // attn out, pixel layout [ch][p]

// ---------------- fp16x2 split helpers --------------------------------------
__device__ __forceinline__ unsigned pk(float a, float b) {
    return (unsigned)__half_as_ushort(__float2half_rn(a)) |
           ((unsigned)__half_as_ushort(__float2half_rn(b)) << 16);
}
__device__ __forceinline__ void split_pack(float a, float b, unsigned& hi, unsigned& lo) {
    __half ha = __float2half_rn(a), hb = __float2half_rn(b);
    hi = (unsigned)__half_as_ushort(ha) | ((unsigned)__half_as_ushort(hb) << 16);
    lo = pk(a - __half2float(ha), b - __half2float(hb));
}

__device__ __forceinline__ void mma_f16(float* d, const unsigned* a, const unsigned* b) {
    asm("mma.sync.aligned.m16n8k16.row.col.f32.f16.f16.f32 "
        "{%0,%1,%2,%3}, {%4,%5,%6,%7}, {%8,%9}, {%0,%1,%2,%3};"
        : "+f"(d[0]), "+f"(d[1]), "+f"(d[2]), "+f"(d[3])
        : "r"(a[0]), "r"(a[1]), "r"(a[2]), "r"(a[3]), "r"(b[0]), "r"(b[1]));
}

// ---------------- cp.async helpers -------------------------------------------
__device__ __forceinline__ unsigned s2u(const void* p) {
    return (unsigned)__cvta_generic_to_shared(p);
}
__device__ __forceinline__ void cpa16(unsigned dst, const void* src) {
    asm volatile("cp.async.ca.shared.global [%0], [%1], 16;" :: "r"(dst), "l"(src));
}
#define CP_COMMIT  asm volatile("cp.async.commit_group;" ::: "memory")
#define CP_WAIT(n) asm volatile("cp.async.wait_group %0;" :: "n"(n) : "memory")

// fp16x2 3-term over one k=32 (real) chunk = 2 m16n8k16 steps.
// SMEM planes hold packed half2 words. Warp tile 64(M) x 32(N).
#define MMAH_K32(APH, APL, AOR, AOK, BPH, BPL, BOK)                           \
    _Pragma("unroll")                                                        \
    for (int ks = 0; ks < 2; ks++) {                                         \
        const int k2w = ks * 8 + tig;                                        \
        unsigned ah[4][4], al[4][4], bh[4][2], bl[4][2];                     \
        _Pragma("unroll")                                                    \
        for (int mt = 0; mt < 4; mt++) {                                     \
            const unsigned* _ph = (APH);                                     \
            const unsigned* _pl = (APL);                                     \
            ah[mt][0] = _ph[0];            al[mt][0] = _pl[0];               \
            ah[mt][1] = _ph[(AOR)];        al[mt][1] = _pl[(AOR)];           \
            ah[mt][2] = _ph[(AOK)];        al[mt][2] = _pl[(AOK)];           \
            ah[mt][3] = _ph[(AOR)+(AOK)];  al[mt][3] = _pl[(AOR)+(AOK)];     \
        }                                                                    \
        _Pragma("unroll")                                                    \
        for (int nt = 0; nt < 4; nt++) {                                     \
            const unsigned* _qh = (BPH);                                     \
            const unsigned* _ql = (BPL);                                     \
            bh[nt][0] = _qh[0];  bh[nt][1] = _qh[(BOK)];                     \
            bl[nt][0] = _ql[0];  bl[nt][1] = _ql[(BOK)];                     \
        }                                                                    \
        _Pragma("unroll")                                                    \
        for (int nt = 0; nt < 4; nt++)                                       \
            _Pragma("unroll")                                                \
            for (int mt = 0; mt < 4; mt++)                                   \
                mma_f16(acc[mt][nt], al[mt], bh[nt]);                        \
        _Pragma("unroll")                                                    \
        for (int nt = 0; nt < 4; nt++)                                       \
            _Pragma("unroll")                                                \
            for (int mt = 0; mt < 4; mt++)                                   \
                mma_f16(acc[mt][nt], ah[mt], bl[nt]);                        \
        _Pragma("unroll")                                                    \
        for (int nt = 0; nt < 4; nt++)                                       \
            _Pragma("unroll")                                                \
            for (int mt = 0; mt < 4; mt++)                                   \
                mma_f16(acc[mt][nt], ah[mt], bh[nt]);                        \
    }

#define ZERO_ACC()                                                            \
    float acc[4][4][4];                                                       \
    _Pragma("unroll")                                                         \
    for (int a = 0; a < 4; a++)                                               \
        _Pragma("unroll")                                                     \
        for (int b = 0; b < 4; b++)                                           \
            _Pragma("unroll")                                                 \
            for (int c = 0; c < 4; c++) acc[a][b][c] = 0.f;

// ============================================================================
// Kernel 1: QKV projection (round-7 core). Epilogue writes packed hi/lo planes.
// ============================================================================
__global__ void __launch_bounds__(256) proj_kernel(
    const float* __restrict__ x,
    const float* __restrict__ wq,
    const float* __restrict__ wkv)
{
    __shared__ __align__(16) unsigned XsH[16 * 136], XsL[16 * 136];
    __shared__ __align__(16) unsigned WsH[128 * 20], WsL[128 * 20];

    const int tid  = threadIdx.x;
    const int lane = tid & 31, warp = tid >> 5;
    const int g = lane >> 2, tig = lane & 3;
    const int wm = (warp >> 2) * 64;       // p
    const int wn = (warp & 3) * 32;        // o
    const int p0 = blockIdx.x * 128;
    const int o0 = blockIdx.y * 128;

    ZERO_ACC();

    for (int kt = 0; kt < 8; kt++) {
        const int c0 = kt * 32;
        #pragma unroll
        for (int q = 0; q < 2; q++) {
            int idx = q * 256 + tid;              // 0..511
            int c2 = idx >> 5, pc = (idx & 31) * 4;
            float4 r0 = *(const float4*)&x[(c0 + 2 * c2)     * NP + p0 + pc];
            float4 r1 = *(const float4*)&x[(c0 + 2 * c2 + 1) * NP + p0 + pc];
            unsigned h0,l0,h1,l1,h2,l2,h3,l3;
            split_pack(r0.x, r1.x, h0, l0); split_pack(r0.y, r1.y, h1, l1);
            split_pack(r0.z, r1.z, h2, l2); split_pack(r0.w, r1.w, h3, l3);
            *(uint4*)&XsH[c2 * 136 + pc] = make_uint4(h0, h1, h2, h3);
            *(uint4*)&XsL[c2 * 136 + pc] = make_uint4(l0, l1, l2, l3);
            int orow = idx >> 2, cg = (idx & 3) * 8;
            int o = o0 + orow;
            const float* arow = (o < 512) ? (wq + o * 256) : (wkv + (o - 512) * 256);
            float4 w0 = *(const float4*)&arow[c0 + cg];
            float4 w1 = *(const float4*)&arow[c0 + cg + 4];
            split_pack(w0.x, w0.y, h0, l0); split_pack(w0.z, w0.w, h1, l1);
            split_pack(w1.x, w1.y, h2, l2); split_pack(w1.z, w1.w, h3, l3);
            *(uint4*)&WsH[orow * 20 + cg / 2] = make_uint4(h0, h1, h2, h3);
            *(uint4*)&WsL[orow * 20 + cg / 2] = make_uint4(l0, l1, l2, l3);
        }
        __syncthreads();
        MMAH_K32(&XsH[k2w * 136 + wm + mt * 16 + g],
                 &XsL[k2w * 136 + wm + mt * 16 + g], 8, 544,
                 &WsH[(wn + nt * 8 + g) * 20 + k2w],
                 &WsL[(wn + nt * 8 + g) * 20 + k2w], 4);
        __syncthreads();
    }

    // epilogue: write packed hi/lo planes.
    #pragma unroll
    for (int nt = 0; nt < 4; nt++) {
        int o   = o0 + wn + nt * 8 + 2 * tig;
        int sel = o >> 9;         // uniform per block
        int oc  = o & 511;
        int gd = (oc >> 6) * 64;
        int dl = oc & 63;
        #pragma unroll
        for (int mt = 0; mt < 4; mt++) {
            #pragma unroll
            for (int r = 0; r < 2; r++) {
                int p  = p0 + wm + mt * 16 + g + r * 8;
                int f  = p >> 14, hh = (p >> 7) & 127, ww = p & 127;
                int gidx = gd + (hh >> 4) * 8 + (ww >> 4);
                int i    = f * 256 + (hh & 15) * 16 + (ww & 15);
                float a = acc[mt][nt][r * 2], b = acc[mt][nt][r * 2 + 1];
                if (sel < 2) {
                    unsigned hi, lo;
                    split_pack(a, b, hi, lo);
                    int off = (gidx * 512 + i) * 32 + (dl >> 1);
                    if (sel == 0) { g_qh[off] = hi; g_ql[off] = lo; }
                    else          { g_kh[off] = hi; g_kl[off] = lo; }
                } else {
                    // V: pack j-pairs (i even with i+1) via lane shuffle (g^1)
                    float pa = __shfl_xor_sync(0xffffffffu, a, 4);
                    float pb = __shfl_xor_sync(0xffffffffu, b, 4);
                    if (!(g & 1)) {
                        unsigned h0, l0, h1, l1;
                        split_pack(a, pa, h0, l0);
                        split_pack(b, pb, h1, l1);
                        int off = (gidx * 256 + (i >> 1)) * 64 + dl;
                        *(uint2*)&g_vh[off] = make_uint2(h0, h1);
                        *(uint2*)&g_vl[off] = make_uint2(l0, l1);
                    }
                }
            }
        }
    }
}

// ============================================================================
// Kernel 2: S = scale * Q @ K^T. Block 128i x 128j, K=64 single-shot cp.async.
// Qs/Ks planes [128][36 words].
// ============================================================================
__global__ void __launch_bounds__(256, 2) qk_kernel()
{
    extern __shared__ __align__(16) unsigned sq[];
    unsigned* QsH = sq;
    unsigned* QsL = sq + 128 * 36;
    unsigned* KsH = sq + 2 * 128 * 36;
    unsigned* KsL = sq + 3 * 128 * 36;

    const int tid  = threadIdx.x;
    const int lane = tid & 31, warp = tid >> 5;
    const int g = lane >> 2, tig = lane & 3;
    const int wm = (warp >> 2) * 64;       // i
    const int wn = (warp & 3) * 32;        // j
    const int gz = blockIdx.z;
    const int i0 = blockIdx.y * 128;
    const int j0 = blockIdx.x * 128;

    // issue all Q/K plane copies (4096 x 16B)
    #pragma unroll
    for (int q = 0; q < 16; q++) {
        int cid = q * 256 + tid;
        int ten = cid >> 11;              // 0=Q, 1=K
        int pl  = (cid >> 10) & 1;
        int row = (cid >> 3) & 127;
        int seg = cid & 7;
        const unsigned* src;
        unsigned dst;
        if (ten == 0) {
            src = (pl ? g_ql : g_qh) + (size_t)(gz * 512 + i0 + row) * 32 + seg * 4;
            dst = s2u((pl ? QsL : QsH) + row * 36 + seg * 4);
        } else {
            src = (pl ? g_kl : g_kh) + (size_t)(gz * 512 + j0 + row) * 32 + seg * 4;
            dst = s2u((pl ? KsL : KsH) + row * 36 + seg * 4);
        }
        cpa16(dst, src);
    }
    CP_COMMIT;

    ZERO_ACC();
    CP_WAIT(0);
    __syncthreads();

    #pragma unroll
    for (int dcb = 0; dcb < 2; dcb++) {
        MMAH_K32(&QsH[(wm + mt * 16 + g) * 36 + dcb * 16 + k2w],
                 &QsL[(wm + mt * 16 + g) * 36 + dcb * 16 + k2w], 288, 4,
                 &KsH[(wn + nt * 8 + g) * 36 + dcb * 16 + k2w],
                 &KsL[(wn + nt * 8 + g) * 36 + dcb * 16 + k2w], 4);
    }

    const float scale = 0.125f;
    #pragma unroll
    for (int mt = 0; mt < 4; mt++) {
        #pragma unroll
        for (int r = 0; r < 2; r++) {
            int i = i0 + wm + mt * 16 + g + r * 8;
            float* srow = &g_s[(gz * 512 + i) * 512 + j0];
            #pragma unroll
            for (int nt = 0; nt < 4; nt++) {
                int jj = wn + nt * 8 + 2 * tig;
                *(float2*)&srow[jj] = make_float2(acc[mt][nt][r * 2] * scale,
                                                  acc[mt][nt][r * 2 + 1] * scale);
            }
        }
    }
}

// ============================================================================
// Kernel 3: row softmax over j (512); writes P as packed hi/lo planes.
// ============================================================================
__global__ void __launch_bounds__(256) softmax_kernel()
{
    const int warp = threadIdx.x >> 5;
    const int lane = threadIdx.x & 31;
    const long long row = (long long)blockIdx.x * 8 + warp;
    const float* rp = g_s + row * 512;

    float4 v[4];
    #pragma unroll
    for (int c = 0; c < 4; c++) v[c] = *(const float4*)&rp[c * 128 + lane * 4];

    float m = -1e30f;
    #pragma unroll
    for (int c = 0; c < 4; c++)
        m = fmaxf(m, fmaxf(fmaxf(v[c].x, v[c].y), fmaxf(v[c].z, v[c].w)));
    #pragma unroll
    for (int s = 16; s > 0; s >>= 1)
        m = fmaxf(m, __shfl_xor_sync(0xffffffffu, m, s));

    float sum = 0.f;
    #pragma unroll
    for (int c = 0; c < 4; c++) {
        v[c].x = __expf(v[c].x - m); v[c].y = __expf(v[c].y - m);
        v[c].z = __expf(v[c].z - m); v[c].w = __expf(v[c].w - m);
        sum += v[c].x + v[c].y + v[c].z + v[c].w;
    }
    #pragma unroll
    for (int s = 16; s > 0; s >>= 1)
        sum += __shfl_xor_sync(0xffffffffu, sum, s);

    const float inv = 1.0f / sum;
    unsigned* ph = g_ph + row * 256;
    unsigned* pl = g_pl + row * 256;
    #pragma unroll
    for (int c = 0; c < 4; c++) {
        float a = v[c].x * inv, b = v[c].y * inv;
        float cc = v[c].z * inv, d = v[c].w * inv;
        unsigned h0, l0, h1, l1;
        split_pack(a, b, h0, l0);
        split_pack(cc, d, h1, l1);
        int w = c * 64 + lane * 2;
        *(uint2*)&ph[w] = make_uint2(h0, h1);
        *(uint2*)&pl[w] = make_uint2(l0, l1);
    }
}

// ============================================================================
// Kernel 4: O = P @ V. Block 128i x 64d, 128 threads.
// cp.async 2-stage pipeline over 16 j-chunks of 32.
// Stage: PsH[128*20] PsL[128*20] VsH[16*72] VsL[16*72] = 7424 words.
// ============================================================================
#define PV_STG 7424
__global__ void __launch_bounds__(128, 3) pv_kernel()
{
    extern __shared__ __align__(16) unsigned sp[];

    const int tid  = threadIdx.x;
    const int lane = tid & 31, warp = tid >> 5;
    const int g = lane >> 2, tig = lane & 3;
    const int wm = (warp >> 1) * 64;       // i
    const int wn = (warp & 1) * 32;        // d
    const int gz = blockIdx.y;
    const int i0 = blockIdx.x * 128;

    ZERO_ACC();

    auto issue = [&](int jt, int buf) {
        unsigned* b   = sp + buf * PV_STG;
        unsigned* psH = b;
        unsigned* psL = b + 2560;
        unsigned* vsH = b + 5120;
        unsigned* vsL = b + 6272;
        #pragma unroll
        for (int q = 0; q < 8; q++) {
            int cid = q * 128 + tid;           // 0..1023
            int pl  = cid >> 9;
            int row = (cid >> 2) & 127;
            int seg = cid & 3;
            const unsigned* src = (pl ? g_pl : g_ph) +
                (size_t)(gz * 512 + i0 + row) * 256 + jt * 16 + seg * 4;
            cpa16(s2u((pl ? psL : psH) + row * 20 + seg * 4), src);
        }
        #pragma unroll
        for (int q = 0; q < 4; q++) {
            int cid = q * 128 + tid;           // 0..511
            int pl  = cid >> 8;
            int r   = (cid >> 4) & 15;
            int seg = cid & 15;
            const unsigned* src = (pl ? g_vl : g_vh) +
                (size_t)(gz * 256 + jt * 16 + r) * 64 + seg * 4;
            cpa16(s2u((pl ? vsL : vsH) + r * 72 + seg * 4), src);
        }
    };

    issue(0, 0);
    CP_COMMIT;
    for (int jt = 0; jt < 16; jt++) {
        if (jt + 1 < 16) issue(jt + 1, (jt + 1) & 1);
        CP_COMMIT;
        CP_WAIT(1);
        __syncthreads();
        unsigned* b   = sp + (jt & 1) * PV_STG;
        unsigned* psH = b;
        unsigned* psL = b + 2560;
        unsigned* vsH = b + 5120;
        unsigned* vsL = b + 6272;
        MMAH_K32(&psH[(wm + mt * 16 + g) * 20 + k2w],
                 &psL[(wm + mt * 16 + g) * 20 + k2w], 160, 4,
                 &vsH[k2w * 72 + wn + nt * 8 + g],
                 &vsL[k2w * 72 + wn + nt * 8 + g], 288);
        __syncthreads();
    }

    #pragma unroll
    for (int mt = 0; mt < 4; mt++) {
        #pragma unroll
        for (int r = 0; r < 2; r++) {
            int i = i0 + wm + mt * 16 + g + r * 8;
            float* orow = &g_ow[(gz * 512 + i) * 64];
            #pragma unroll
            for (int nt = 0; nt < 4; nt++) {
                int d = wn + nt * 8 + 2 * tig;
                *(float2*)&orow[d] = make_float2(acc[mt][nt][r * 2],
                                                 acc[mt][nt][r * 2 + 1]);
            }
        }
    }
}

// ============================================================================
// Kernel 5: window layout [g][i][d] -> pixel layout [ch][p] via SMEM staging.
// ============================================================================
__global__ void __launch_bounds__(256) transpose_kernel()
{
    __shared__ __align__(16) float T[128][68];

    const int tid = threadIdx.x;
    const int g  = blockIdx.y;
    const int i0 = blockIdx.x * 128;
    const float* src = g_ow + (g * 512 + i0) * 64;

    #pragma unroll
    for (int q = 0; q < 8; q++) {
        int idx = q * 256 + tid;       // 0..2047
        int row = idx >> 4;            // 0..127
        int d4  = (idx & 15) * 4;
        *(float4*)&T[row][d4] = *(const float4*)&src[row * 64 + d4];
    }
    __syncthreads();

    const int head = g >> 6;
    const int win  = g & 63;
    const int wxv  = win >> 3, wyv = win & 7;

    #pragma unroll
    for (int q = 0; q < 2; q++) {
        int t   = q * 256 + tid;       // 0..511
        int d   = t & 63;
        int run = t >> 6;              // 0..7
        int ib  = run * 16;
        int ig  = i0 + ib;
        int f   = ig >> 8;
        int w1  = (ig >> 4) & 15;
        int pbase = f * 16384 + (wxv * 16 + w1) * 128 + wyv * 16;
        float* dst = g_op + (head * 64 + d) * NP + pbase;
        #pragma unroll
        for (int e = 0; e < 4; e++) {
            float4 v4;
            v4.x = T[ib + e * 4 + 0][d];
            v4.y = T[ib + e * 4 + 1][d];
            v4.z = T[ib + e * 4 + 2][d];
            v4.w = T[ib + e * 4 + 3][d];
            *(float4*)&dst[e * 4] = v4;
        }
    }
}

// ============================================================================
// Kernel 6: final projection + bias (round-7). Block 128o(M) x 128p(N), K=512.
// ============================================================================
__global__ void __launch_bounds__(256) out_kernel(
    const float* __restrict__ wo,
    const float* __restrict__ bo,
    float* __restrict__ out)
{
    __shared__ __align__(16) unsigned BsH[16 * 136], BsL[16 * 136];
    __shared__ __align__(16) unsigned WsH[128 * 20], WsL[128 * 20];

    const int tid  = threadIdx.x;
    const int lane = tid & 31, warp = tid >> 5;
    const int g = lane >> 2, tig = lane & 3;
    const int wm = (warp >> 2) * 64;       // o
    const int wn = (warp & 3) * 32;        // p
    const int p0 = blockIdx.x * 128;
    const int o0 = blockIdx.y * 128;

    ZERO_ACC();

    for (int kt = 0; kt < 16; kt++) {
        const int c0 = kt * 32;
        #pragma unroll
        for (int q = 0; q < 2; q++) {
            int idx = q * 256 + tid;
            int c2 = idx >> 5, pc = (idx & 31) * 4;
            float4 r0 = *(const float4*)&g_op[(c0 + 2 * c2)     * NP + p0 + pc];
            float4 r1 = *(const float4*)&g_op[(c0 + 2 * c2 + 1) * NP + p0 + pc];
            unsigned h0,l0,h1,l1,h2,l2,h3,l3;
            split_pack(r0.x, r1.x, h0, l0); split_pack(r0.y, r1.y, h1, l1);
            split_pack(r0.z, r1.z, h2, l2); split_pack(r0.w, r1.w, h3, l3);
            *(uint4*)&BsH[c2 * 136 + pc] = make_uint4(h0, h1, h2, h3);
            *(uint4*)&BsL[c2 * 136 + pc] = make_uint4(l0, l1, l2, l3);
            int orow = idx >> 2, cg = (idx & 3) * 8;
            float4 w0 = *(const float4*)&wo[(o0 + orow) * 512 + c0 + cg];
            float4 w1 = *(const float4*)&wo[(o0 + orow) * 512 + c0 + cg + 4];
            split_pack(w0.x, w0.y, h0, l0); split_pack(w0.z, w0.w, h1, l1);
            split_pack(w1.x, w1.y, h2, l2); split_pack(w1.z, w1.w, h3, l3);
            *(uint4*)&WsH[orow * 20 + cg / 2] = make_uint4(h0, h1, h2, h3);
            *(uint4*)&WsL[orow * 20 + cg / 2] = make_uint4(l0, l1, l2, l3);
        }
        __syncthreads();
        MMAH_K32(&WsH[(wm + mt * 16 + g) * 20 + k2w],
                 &WsL[(wm + mt * 16 + g) * 20 + k2w], 160, 4,
                 &BsH[k2w * 136 + wn + nt * 8 + g],
                 &BsL[k2w * 136 + wn + nt * 8 + g], 544);
        __syncthreads();
    }

    #pragma unroll
    for (int mt = 0; mt < 4; mt++) {
        int o  = o0 + wm + mt * 16 + g;
        float b0 = bo[o];
        float b1 = bo[o + 8];
        #pragma unroll
        for (int nt = 0; nt < 4; nt++) {
            int p = p0 + wn + nt * 8 + 2 * tig;
            *(float2*)&out[o * NP + p] =
                make_float2(acc[mt][nt][0] + b0, acc[mt][nt][1] + b0);
            *(float2*)&out[(o + 8) * NP + p] =
                make_float2(acc[mt][nt][2] + b1, acc[mt][nt][3] + b1);
        }
    }
}

// ============================================================================
extern "C" void kernel_launch(void* const* d_in, const int* in_sizes, int n_in,
                              void* d_out, int out_size)
{
    const float* x   = (const float*)d_in[0];
    const float* wq  = (const float*)d_in[1];
    const float* wkv = (const float*)d_in[2];
    const float* wo  = (const float*)d_in[3];
    const float* bo  = (const float*)d_in[4];
    float* out = (float*)d_out;

    const int QK_SMEM = 4 * 128 * 36 * 4;      // 73728 B
    const int PV_SMEM = 2 * PV_STG * 4;        // 59392 B

    static int attr_done = 0;
    if (!attr_done) {
        cudaFuncSetAttribute(qk_kernel, cudaFuncAttributeMaxDynamicSharedMemorySize, QK_SMEM);
        cudaFuncSetAttribute(pv_kernel, cudaFuncAttributeMaxDynamicSharedMemorySize, PV_SMEM);
        attr_done = 1;
    }

    proj_kernel     <<<dim3(NP / 128, 1536 / 128), 256>>>(x, wq, wkv);
    qk_kernel       <<<dim3(4, 4, NG),             256, QK_SMEM>>>();
    softmax_kernel  <<<dim3(NG * SEQ / 8),         256>>>();
    pv_kernel       <<<dim3(4, NG),                128, PV_SMEM>>>();
    transpose_kernel<<<dim3(4, NG),                256>>>();
    out_kernel      <<<dim3(NP / 128, 256 / 128),  256>>>(wo, bo, out);
}

// round 9
// speedup vs baseline: 2.4626x; 1.2263x over previous
#include <cuda_runtime.h>
#include <cuda_fp16.h>

#define NP 32768          // pixels = F*H*W = 2*128*128
#define SEQ 512           // window sequence length
#define NG 512            // head*window groups = 8*64

// ---------------- scratch (static __device__; no allocation APIs) ----------
// Q/K planes: [g][i][32 d-pair words], hi & lo. Q is pre-scaled by 0.125.
__device__ unsigned g_qh[NG * SEQ * 32], g_ql[NG * SEQ * 32];
__device__ unsigned g_kh[NG * SEQ * 32], g_kl[NG * SEQ * 32];
// V planes: [g][j2][64 d words] (j-pairs packed per word)
__device__ unsigned g_vh[NG * 256 * 64], g_vl[NG * 256 * 64];
__device__ float    g_ow[NG * SEQ * 64];   // attn out, window layout
__device__ float    g_op[512 * NP];        // attn out, pixel layout [ch][p]

// ---------------- fp16x2 split helpers --------------------------------------
__device__ __forceinline__ unsigned pk(float a, float b) {
    return (unsigned)__half_as_ushort(__float2half_rn(a)) |
           ((unsigned)__half_as_ushort(__float2half_rn(b)) << 16);
}
__device__ __forceinline__ void split_pack(float a, float b, unsigned& hi, unsigned& lo) {
    __half ha = __float2half_rn(a), hb = __float2half_rn(b);
    hi = (unsigned)__half_as_ushort(ha) | ((unsigned)__half_as_ushort(hb) << 16);
    lo = pk(a - __half2float(ha), b - __half2float(hb));
}

__device__ __forceinline__ void mma_f16(float* d, const unsigned* a, const unsigned* b) {
    asm("mma.sync.aligned.m16n8k16.row.col.f32.f16.f16.f32 "
        "{%0,%1,%2,%3}, {%4,%5,%6,%7}, {%8,%9}, {%0,%1,%2,%3};"
        : "+f"(d[0]), "+f"(d[1]), "+f"(d[2]), "+f"(d[3])
        : "r"(a[0]), "r"(a[1]), "r"(a[2]), "r"(a[3]), "r"(b[0]), "r"(b[1]));
}

// ---------------- cp.async helpers -------------------------------------------
__device__ __forceinline__ unsigned s2u(const void* p) {
    return (unsigned)__cvta_generic_to_shared(p);
}
__device__ __forceinline__ void cpa16(unsigned dst, const void* src) {
    asm volatile("cp.async.ca.shared.global [%0], [%1], 16;" :: "r"(dst), "l"(src));
}
#define CP_COMMIT  asm volatile("cp.async.commit_group;" ::: "memory")
#define CP_WAIT(n) asm volatile("cp.async.wait_group %0;" :: "n"(n) : "memory")

// fp16x2 3-term over one k=32 (real) chunk = 2 m16n8k16 steps (GEMM kernels).
#define MMAH_K32(APH, APL, AOR, AOK, BPH, BPL, BOK)                           \
    _Pragma("unroll")                                                        \
    for (int ks = 0; ks < 2; ks++) {                                         \
        const int k2w = ks * 8 + tig;                                        \
        unsigned ah[4][4], al[4][4], bh[4][2], bl[4][2];                     \
        _Pragma("unroll")                                                    \
        for (int mt = 0; mt < 4; mt++) {                                     \
            const unsigned* _ph = (APH);                                     \
            const unsigned* _pl = (APL);                                     \
            ah[mt][0] = _ph[0];            al[mt][0] = _pl[0];               \
            ah[mt][1] = _ph[(AOR)];        al[mt][1] = _pl[(AOR)];           \
            ah[mt][2] = _ph[(AOK)];        al[mt][2] = _pl[(AOK)];           \
            ah[mt][3] = _ph[(AOR)+(AOK)];  al[mt][3] = _pl[(AOR)+(AOK)];     \
        }                                                                    \
        _Pragma("unroll")                                                    \
        for (int nt = 0; nt < 4; nt++) {                                     \
            const unsigned* _qh = (BPH);                                     \
            const unsigned* _ql = (BPL);                                     \
            bh[nt][0] = _qh[0];  bh[nt][1] = _qh[(BOK)];                     \
            bl[nt][0] = _ql[0];  bl[nt][1] = _ql[(BOK)];                     \
        }                                                                    \
        _Pragma("unroll")                                                    \
        for (int nt = 0; nt < 4; nt++)                                       \
            _Pragma("unroll")                                                \
            for (int mt = 0; mt < 4; mt++)                                   \
                mma_f16(acc[mt][nt], al[mt], bh[nt]);                        \
        _Pragma("unroll")                                                    \
        for (int nt = 0; nt < 4; nt++)                                       \
            _Pragma("unroll")                                                \
            for (int mt = 0; mt < 4; mt++)                                   \
                mma_f16(acc[mt][nt], ah[mt], bl[nt]);                        \
        _Pragma("unroll")                                                    \
        for (int nt = 0; nt < 4; nt++)                                       \
            _Pragma("unroll")                                                \
            for (int mt = 0; mt < 4; mt++)                                   \
                mma_f16(acc[mt][nt], ah[mt], bh[nt]);                        \
    }

#define ZERO_ACC()                                                            \
    float acc[4][4][4];                                                       \
    _Pragma("unroll")                                                         \
    for (int a = 0; a < 4; a++)                                               \
        _Pragma("unroll")                                                     \
        for (int b = 0; b < 4; b++)                                           \
            _Pragma("unroll")                                                 \
            for (int c = 0; c < 4; c++) acc[a][b][c] = 0.f;

// ============================================================================
// Kernel 1: QKV projection. Epilogue writes packed hi/lo planes; Q pre-scaled.
// ============================================================================
__global__ void __launch_bounds__(256) proj_kernel(
    const float* __restrict__ x,
    const float* __restrict__ wq,
    const float* __restrict__ wkv)
{
    __shared__ __align__(16) unsigned XsH[16 * 136], XsL[16 * 136];
    __shared__ __align__(16) unsigned WsH[128 * 20], WsL[128 * 20];

    const int tid  = threadIdx.x;
    const int lane = tid & 31, warp = tid >> 5;
    const int g = lane >> 2, tig = lane & 3;
    const int wm = (warp >> 2) * 64;       // p
    const int wn = (warp & 3) * 32;        // o
    const int p0 = blockIdx.x * 128;
    const int o0 = blockIdx.y * 128;

    ZERO_ACC();

    for (int kt = 0; kt < 8; kt++) {
        const int c0 = kt * 32;
        #pragma unroll
        for (int q = 0; q < 2; q++) {
            int idx = q * 256 + tid;              // 0..511
            int c2 = idx >> 5, pc = (idx & 31) * 4;
            float4 r0 = *(const float4*)&x[(c0 + 2 * c2)     * NP + p0 + pc];
            float4 r1 = *(const float4*)&x[(c0 + 2 * c2 + 1) * NP + p0 + pc];
            unsigned h0,l0,h1,l1,h2,l2,h3,l3;
            split_pack(r0.x, r1.x, h0, l0); split_pack(r0.y, r1.y, h1, l1);
            split_pack(r0.z, r1.z, h2, l2); split_pack(r0.w, r1.w, h3, l3);
            *(uint4*)&XsH[c2 * 136 + pc] = make_uint4(h0, h1, h2, h3);
            *(uint4*)&XsL[c2 * 136 + pc] = make_uint4(l0, l1, l2, l3);
            int orow = idx >> 2, cg = (idx & 3) * 8;
            int o = o0 + orow;
            const float* arow = (o < 512) ? (wq + o * 256) : (wkv + (o - 512) * 256);
            float4 w0 = *(const float4*)&arow[c0 + cg];
            float4 w1 = *(const float4*)&arow[c0 + cg + 4];
            split_pack(w0.x, w0.y, h0, l0); split_pack(w0.z, w0.w, h1, l1);
            split_pack(w1.x, w1.y, h2, l2); split_pack(w1.z, w1.w, h3, l3);
            *(uint4*)&WsH[orow * 20 + cg / 2] = make_uint4(h0, h1, h2, h3);
            *(uint4*)&WsL[orow * 20 + cg / 2] = make_uint4(l0, l1, l2, l3);
        }
        __syncthreads();
        MMAH_K32(&XsH[k2w * 136 + wm + mt * 16 + g],
                 &XsL[k2w * 136 + wm + mt * 16 + g], 8, 544,
                 &WsH[(wn + nt * 8 + g) * 20 + k2w],
                 &WsL[(wn + nt * 8 + g) * 20 + k2w], 4);
        __syncthreads();
    }

    #pragma unroll
    for (int nt = 0; nt < 4; nt++) {
        int o   = o0 + wn + nt * 8 + 2 * tig;
        int sel = o >> 9;         // uniform per block
        int oc  = o & 511;
        int gd = (oc >> 6) * 64;
        int dl = oc & 63;
        #pragma unroll
        for (int mt = 0; mt < 4; mt++) {
            #pragma unroll
            for (int r = 0; r < 2; r++) {
                int p  = p0 + wm + mt * 16 + g + r * 8;
                int f  = p >> 14, hh = (p >> 7) & 127, ww = p & 127;
                int gidx = gd + (hh >> 4) * 8 + (ww >> 4);
                int i    = f * 256 + (hh & 15) * 16 + (ww & 15);
                float a = acc[mt][nt][r * 2], b = acc[mt][nt][r * 2 + 1];
                if (sel == 0) {
                    unsigned hi, lo;
                    split_pack(a * 0.125f, b * 0.125f, hi, lo);  // fold scale
                    int off = (gidx * 512 + i) * 32 + (dl >> 1);
                    g_qh[off] = hi; g_ql[off] = lo;
                } else if (sel == 1) {
                    unsigned hi, lo;
                    split_pack(a, b, hi, lo);
                    int off = (gidx * 512 + i) * 32 + (dl >> 1);
                    g_kh[off] = hi; g_kl[off] = lo;
                } else {
                    float pa = __shfl_xor_sync(0xffffffffu, a, 4);
                    float pb = __shfl_xor_sync(0xffffffffu, b, 4);
                    if (!(g & 1)) {
                        unsigned h0, l0, h1, l1;
                        split_pack(a, pa, h0, l0);
                        split_pack(b, pb, h1, l1);
                        int off = (gidx * 256 + (i >> 1)) * 64 + dl;
                        *(uint2*)&g_vh[off] = make_uint2(h0, h1);
                        *(uint2*)&g_vl[off] = make_uint2(l0, l1);
                    }
                }
            }
        }
    }
}

// ============================================================================
// Kernel 2: fused flash attention. Block = 4 warps x 16 i-rows = 64 i.
// Grid (8 i-tiles, 512 groups) — same-group blocks co-run, share K/V via L2.
// Streams j in chunks of 64 via 2-stage cp.async. P stays in registers
// (QK D-fragment == PV A-fragment layout).
// Stage: KH[64*36] KL[64*36] VH[32*72] VL[32*72] = 9216 words (36 KB).
// ============================================================================
#define FA_STG 9216
__global__ void __launch_bounds__(128, 3) attn_kernel()
{
    extern __shared__ __align__(16) unsigned sf[];

    const int tid  = threadIdx.x;
    const int lane = tid & 31, wid = tid >> 5;
    const int g = lane >> 2, tig = lane & 3;
    const int gz = blockIdx.y;
    const int i0 = blockIdx.x * 64;

    // resident Q fragments (pre-scaled by 0.125 in proj)
    unsigned qah[4][4], qal[4][4];
    {
        const size_t qrow = (size_t)(gz * 512 + i0 + wid * 16 + g) * 32;
        #pragma unroll
        for (int ks = 0; ks < 4; ks++) {
            int w = ks * 8 + tig;
            qah[ks][0] = g_qh[qrow + w];
            qah[ks][1] = g_qh[qrow + 256 + w];
            qah[ks][2] = g_qh[qrow + w + 4];
            qah[ks][3] = g_qh[qrow + 256 + w + 4];
            qal[ks][0] = g_ql[qrow + w];
            qal[ks][1] = g_ql[qrow + 256 + w];
            qal[ks][2] = g_ql[qrow + w + 4];
            qal[ks][3] = g_ql[qrow + 256 + w + 4];
        }
    }

    float acc_o[8][4];
    #pragma unroll
    for (int a = 0; a < 8; a++)
        #pragma unroll
        for (int b = 0; b < 4; b++) acc_o[a][b] = 0.f;
    float m0 = -1e30f, m1 = -1e30f, l0 = 0.f, l1 = 0.f;

    auto issue = [&](int jt, int buf) {
        unsigned* b = sf + buf * FA_STG;
        #pragma unroll
        for (int q = 0; q < 8; q++) {              // K planes: 1024 x 16B
            int cid = q * 128 + tid;
            int pl = cid >> 9, row = (cid >> 3) & 63, seg = cid & 7;
            const unsigned* src = (pl ? g_kl : g_kh) +
                (size_t)(gz * 512 + jt * 64 + row) * 32 + seg * 4;
            cpa16(s2u(b + pl * 2304 + row * 36 + seg * 4), src);
        }
        #pragma unroll
        for (int q = 0; q < 8; q++) {              // V planes: 1024 x 16B
            int cid = q * 128 + tid;
            int pl = cid >> 9, r = (cid >> 4) & 31, seg = cid & 15;
            const unsigned* src = (pl ? g_vl : g_vh) +
                (size_t)(gz * 256 + jt * 32 + r) * 64 + seg * 4;
            cpa16(s2u(b + 4608 + pl * 2304 + r * 72 + seg * 4), src);
        }
    };

    issue(0, 0);
    CP_COMMIT;
    for (int jt = 0; jt < 8; jt++) {
        if (jt + 1 < 8) issue(jt + 1, (jt + 1) & 1);
        CP_COMMIT;
        CP_WAIT(1);
        __syncthreads();
        unsigned* b  = sf + (jt & 1) * FA_STG;
        unsigned* KH = b;
        unsigned* KL = b + 2304;
        unsigned* VH = b + 4608;
        unsigned* VL = b + 6912;

        // ---- S = Q @ K^T over this 64j chunk (16i x 64j per warp) ----
        float sacc[8][4];
        #pragma unroll
        for (int a = 0; a < 8; a++)
            #pragma unroll
            for (int c = 0; c < 4; c++) sacc[a][c] = 0.f;

        #pragma unroll
        for (int ks = 0; ks < 4; ks++) {
            #pragma unroll
            for (int h = 0; h < 2; h++) {
                unsigned bh[4][2], bl[4][2];
                #pragma unroll
                for (int q = 0; q < 4; q++) {
                    int nt = h * 4 + q;
                    const unsigned* ph = &KH[(nt * 8 + g) * 36 + ks * 8 + tig];
                    const unsigned* pl = &KL[(nt * 8 + g) * 36 + ks * 8 + tig];
                    bh[q][0] = ph[0]; bh[q][1] = ph[4];
                    bl[q][0] = pl[0]; bl[q][1] = pl[4];
                }
                #pragma unroll
                for (int q = 0; q < 4; q++) mma_f16(sacc[h * 4 + q], qal[ks], bh[q]);
                #pragma unroll
                for (int q = 0; q < 4; q++) mma_f16(sacc[h * 4 + q], qah[ks], bl[q]);
                #pragma unroll
                for (int q = 0; q < 4; q++) mma_f16(sacc[h * 4 + q], qah[ks], bh[q]);
            }
        }

        // ---- online softmax (rows g and g+8; 4 tig lanes share a row) ----
        float mx0 = -1e30f, mx1 = -1e30f;
        #pragma unroll
        for (int nt = 0; nt < 8; nt++) {
            mx0 = fmaxf(mx0, fmaxf(sacc[nt][0], sacc[nt][1]));
            mx1 = fmaxf(mx1, fmaxf(sacc[nt][2], sacc[nt][3]));
        }
        mx0 = fmaxf(mx0, __shfl_xor_sync(0xffffffffu, mx0, 1));
        mx0 = fmaxf(mx0, __shfl_xor_sync(0xffffffffu, mx0, 2));
        mx1 = fmaxf(mx1, __shfl_xor_sync(0xffffffffu, mx1, 1));
        mx1 = fmaxf(mx1, __shfl_xor_sync(0xffffffffu, mx1, 2));
        float mn0 = fmaxf(m0, mx0), mn1 = fmaxf(m1, mx1);
        float c0 = __expf(m0 - mn0), c1 = __expf(m1 - mn1);
        m0 = mn0; m1 = mn1;
        float s0 = 0.f, s1 = 0.f;
        #pragma unroll
        for (int nt = 0; nt < 8; nt++) {
            sacc[nt][0] = __expf(sacc[nt][0] - mn0);
            sacc[nt][1] = __expf(sacc[nt][1] - mn0);
            sacc[nt][2] = __expf(sacc[nt][2] - mn1);
            sacc[nt][3] = __expf(sacc[nt][3] - mn1);
            s0 += sacc[nt][0] + sacc[nt][1];
            s1 += sacc[nt][2] + sacc[nt][3];
        }
        s0 += __shfl_xor_sync(0xffffffffu, s0, 1);
        s0 += __shfl_xor_sync(0xffffffffu, s0, 2);
        s1 += __shfl_xor_sync(0xffffffffu, s1, 1);
        s1 += __shfl_xor_sync(0xffffffffu, s1, 2);
        l0 = l0 * c0 + s0;
        l1 = l1 * c1 + s1;
        #pragma unroll
        for (int nt = 0; nt < 8; nt++) {
            acc_o[nt][0] *= c0; acc_o[nt][1] *= c0;
            acc_o[nt][2] *= c1; acc_o[nt][3] *= c1;
        }

        // ---- O += P @ V  (P from registers: D-frag == A-frag layout) ----
        #pragma unroll
        for (int kt = 0; kt < 4; kt++) {
            unsigned pah[4], pal[4];
            split_pack(sacc[2 * kt][0],     sacc[2 * kt][1],     pah[0], pal[0]);
            split_pack(sacc[2 * kt][2],     sacc[2 * kt][3],     pah[1], pal[1]);
            split_pack(sacc[2 * kt + 1][0], sacc[2 * kt + 1][1], pah[2], pal[2]);
            split_pack(sacc[2 * kt + 1][2], sacc[2 * kt + 1][3], pah[3], pal[3]);
            #pragma unroll
            for (int h = 0; h < 2; h++) {
                unsigned bh[4][2], bl[4][2];
                #pragma unroll
                for (int q = 0; q < 4; q++) {
                    int nt = h * 4 + q;
                    const unsigned* ph = &VH[(kt * 8 + tig) * 72 + nt * 8 + g];
                    const unsigned* pl = &VL[(kt * 8 + tig) * 72 + nt * 8 + g];
                    bh[q][0] = ph[0]; bh[q][1] = ph[288];
                    bl[q][0] = pl[0]; bl[q][1] = pl[288];
                }
                #pragma unroll
                for (int q = 0; q < 4; q++) mma_f16(acc_o[h * 4 + q], pal, bh[q]);
                #pragma unroll
                for (int q = 0; q < 4; q++) mma_f16(acc_o[h * 4 + q], pah, bl[q]);
                #pragma unroll
                for (int q = 0; q < 4; q++) mma_f16(acc_o[h * 4 + q], pah, bh[q]);
            }
        }
        __syncthreads();
    }

    // ---- epilogue: O / l -> g_ow [g][i][d] ----
    float rl0 = __fdividef(1.0f, l0), rl1 = __fdividef(1.0f, l1);
    int ia = i0 + wid * 16 + g;
    float* row0 = &g_ow[(gz * 512 + ia) * 64];
    float* row1 = &g_ow[(gz * 512 + ia + 8) * 64];
    #pragma unroll
    for (int nt = 0; nt < 8; nt++) {
        int d = nt * 8 + 2 * tig;
        *(float2*)&row0[d] = make_float2(acc_o[nt][0] * rl0, acc_o[nt][1] * rl0);
        *(float2*)&row1[d] = make_float2(acc_o[nt][2] * rl1, acc_o[nt][3] * rl1);
    }
}

// ============================================================================
// Kernel 3: window layout [g][i][d] -> pixel layout [ch][p] via SMEM staging.
// ============================================================================
__global__ void __launch_bounds__(256) transpose_kernel()
{
    __shared__ __align__(16) float T[128][68];

    const int tid = threadIdx.x;
    const int g  = blockIdx.y;
    const int i0 = blockIdx.x * 128;
    const float* src = g_ow + (g * 512 + i0) * 64;

    #pragma unroll
    for (int q = 0; q < 8; q++) {
        int idx = q * 256 + tid;       // 0..2047
        int row = idx >> 4;            // 0..127
        int d4  = (idx & 15) * 4;
        *(float4*)&T[row][d4] = *(const float4*)&src[row * 64 + d4];
    }
    __syncthreads();

    const int head = g >> 6;
    const int win  = g & 63;
    const int wxv  = win >> 3, wyv = win & 7;

    #pragma unroll
    for (int q = 0; q < 2; q++) {
        int t   = q * 256 + tid;       // 0..511
        int d   = t & 63;
        int run = t >> 6;              // 0..7
        int ib  = run * 16;
        int ig  = i0 + ib;
        int f   = ig >> 8;
        int w1  = (ig >> 4) & 15;
        int pbase = f * 16384 + (wxv * 16 + w1) * 128 + wyv * 16;
        float* dst = g_op + (head * 64 + d) * NP + pbase;
        #pragma unroll
        for (int e = 0; e < 4; e++) {
            float4 v4;
            v4.x = T[ib + e * 4 + 0][d];
            v4.y = T[ib + e * 4 + 1][d];
            v4.z = T[ib + e * 4 + 2][d];
            v4.w = T[ib + e * 4 + 3][d];
            *(float4*)&dst[e * 4] = v4;
        }
    }
}

// ============================================================================
// Kernel 4: final projection + bias. Block 128o(M) x 128p(N), K=512.
// ============================================================================
__global__ void __launch_bounds__(256) out_kernel(
    const float* __restrict__ wo,
    const float* __restrict__ bo,
    float* __restrict__ out)
{
    __shared__ __align__(16) unsigned BsH[16 * 136], BsL[16 * 136];
    __shared__ __align__(16) unsigned WsH[128 * 20], WsL[128 * 20];

    const int tid  = threadIdx.x;
    const int lane = tid & 31, warp = tid >> 5;
    const int g = lane >> 2, tig = lane & 3;
    const int wm = (warp >> 2) * 64;       // o
    const int wn = (warp & 3) * 32;        // p
    const int p0 = blockIdx.x * 128;
    const int o0 = blockIdx.y * 128;

    ZERO_ACC();

    for (int kt = 0; kt < 16; kt++) {
        const int c0 = kt * 32;
        #pragma unroll
        for (int q = 0; q < 2; q++) {
            int idx = q * 256 + tid;
            int c2 = idx >> 5, pc = (idx & 31) * 4;
            float4 r0 = *(const float4*)&g_op[(c0 + 2 * c2)     * NP + p0 + pc];
            float4 r1 = *(const float4*)&g_op[(c0 + 2 * c2 + 1) * NP + p0 + pc];
            unsigned h0,l0,h1,l1,h2,l2,h3,l3;
            split_pack(r0.x, r1.x, h0, l0); split_pack(r0.y, r1.y, h1, l1);
            split_pack(r0.z, r1.z, h2, l2); split_pack(r0.w, r1.w, h3, l3);
            *(uint4*)&BsH[c2 * 136 + pc] = make_uint4(h0, h1, h2, h3);
            *(uint4*)&BsL[c2 * 136 + pc] = make_uint4(l0, l1, l2, l3);
            int orow = idx >> 2, cg = (idx & 3) * 8;
            float4 w0 = *(const float4*)&wo[(o0 + orow) * 512 + c0 + cg];
            float4 w1 = *(const float4*)&wo[(o0 + orow) * 512 + c0 + cg + 4];
            split_pack(w0.x, w0.y, h0, l0); split_pack(w0.z, w0.w, h1, l1);
            split_pack(w1.x, w1.y, h2, l2); split_pack(w1.z, w1.w, h3, l3);
            *(uint4*)&WsH[orow * 20 + cg / 2] = make_uint4(h0, h1, h2, h3);
            *(uint4*)&WsL[orow * 20 + cg / 2] = make_uint4(l0, l1, l2, l3);
        }
        __syncthreads();
        MMAH_K32(&WsH[(wm + mt * 16 + g) * 20 + k2w],
                 &WsL[(wm + mt * 16 + g) * 20 + k2w], 160, 4,
                 &BsH[k2w * 136 + wn + nt * 8 + g],
                 &BsL[k2w * 136 + wn + nt * 8 + g], 544);
        __syncthreads();
    }

    #pragma unroll
    for (int mt = 0; mt < 4; mt++) {
        int o  = o0 + wm + mt * 16 + g;
        float b0 = bo[o];
        float b1 = bo[o + 8];
        #pragma unroll
        for (int nt = 0; nt < 4; nt++) {
            int p = p0 + wn + nt * 8 + 2 * tig;
            *(float2*)&out[o * NP + p] =
                make_float2(acc[mt][nt][0] + b0, acc[mt][nt][1] + b0);
            *(float2*)&out[(o + 8) * NP + p] =
                make_float2(acc[mt][nt][2] + b1, acc[mt][nt][3] + b1);
        }
    }
}

// ============================================================================
extern "C" void kernel_launch(void* const* d_in, const int* in_sizes, int n_in,
                              void* d_out, int out_size)
{
    const float* x   = (const float*)d_in[0];
    const float* wq  = (const float*)d_in[1];
    const float* wkv = (const float*)d_in[2];
    const float* wo  = (const float*)d_in[3];
    const float* bo  = (const float*)d_in[4];
    float* out = (float*)d_out;

    const int FA_SMEM = 2 * FA_STG * 4;        // 73728 B

    static int attr_done = 0;
    if (!attr_done) {
        cudaFuncSetAttribute(attn_kernel, cudaFuncAttributeMaxDynamicSharedMemorySize, FA_SMEM);
        attr_done = 1;
    }

    proj_kernel     <<<dim3(NP / 128, 1536 / 128), 256>>>(x, wq, wkv);
    attn_kernel     <<<dim3(8, NG),                128, FA_SMEM>>>();
    transpose_kernel<<<dim3(4, NG),                256>>>();
    out_kernel      <<<dim3(NP / 128, 256 / 128),  256>>>(wo, bo, out);
}

// round 10
// speedup vs baseline: 2.6887x; 1.0918x over previous
#include <cuda_runtime.h>
#include <cuda_fp16.h>

#define NP 32768          // pixels = F*H*W = 2*128*128
#define SEQ 512           // window sequence length
#define NG 512            // head*window groups = 8*64

// ---------------- scratch (static __device__; no allocation APIs) ----------
// x packed planes: [c2=128][32768 p] words (c-pairs per word)
__device__ unsigned g_xh[128 * NP], g_xl[128 * NP];
// qkv weight planes: [1536 o][128 c2 words]
__device__ unsigned g_wh[1536 * 128], g_wl[1536 * 128];
// wo planes: [512 o][256 c2 words]
__device__ unsigned g_woh[512 * 256], g_wol[512 * 256];
// Q/K planes: [g][i][32 d-pair words], hi & lo. Q is pre-scaled by 0.125.
__device__ unsigned g_qh[NG * SEQ * 32], g_ql[NG * SEQ * 32];
__device__ unsigned g_kh[NG * SEQ * 32], g_kl[NG * SEQ * 32];
// V planes: [g][j2][64 d words] (j-pairs packed per word)
__device__ unsigned g_vh[NG * 256 * 64], g_vl[NG * 256 * 64];
__device__ float    g_ow[NG * SEQ * 64];   // attn out, window layout
// attn out pixel layout, packed planes: [c2=256][32768 p] words
__device__ unsigned g_oph[256 * NP], g_opl[256 * NP];

// ---------------- fp16x2 split helpers --------------------------------------
__device__ __forceinline__ unsigned pk(float a, float b) {
    return (unsigned)__half_as_ushort(__float2half_rn(a)) |
           ((unsigned)__half_as_ushort(__float2half_rn(b)) << 16);
}
__device__ __forceinline__ void split_pack(float a, float b, unsigned& hi, unsigned& lo) {
    __half ha = __float2half_rn(a), hb = __float2half_rn(b);
    hi = (unsigned)__half_as_ushort(ha) | ((unsigned)__half_as_ushort(hb) << 16);
    lo = pk(a - __half2float(ha), b - __half2float(hb));
}

__device__ __forceinline__ void mma_f16(float* d, const unsigned* a, const unsigned* b) {
    asm("mma.sync.aligned.m16n8k16.row.col.f32.f16.f16.f32 "
        "{%0,%1,%2,%3}, {%4,%5,%6,%7}, {%8,%9}, {%0,%1,%2,%3};"
        : "+f"(d[0]), "+f"(d[1]), "+f"(d[2]), "+f"(d[3])
        : "r"(a[0]), "r"(a[1]), "r"(a[2]), "r"(a[3]), "r"(b[0]), "r"(b[1]));
}

// ---------------- cp.async helpers -------------------------------------------
__device__ __forceinline__ unsigned s2u(const void* p) {
    return (unsigned)__cvta_generic_to_shared(p);
}
__device__ __forceinline__ void cpa16(unsigned dst, const void* src) {
    asm volatile("cp.async.ca.shared.global [%0], [%1], 16;" :: "r"(dst), "l"(src));
}
#define CP_COMMIT  asm volatile("cp.async.commit_group;" ::: "memory")
#define CP_WAIT(n) asm volatile("cp.async.wait_group %0;" :: "n"(n) : "memory")

// fp16x2 3-term over one k=32 (real) chunk = 2 m16n8k16 steps.
#define MMAH_K32(APH, APL, AOR, AOK, BPH, BPL, BOK)                           \
    _Pragma("unroll")                                                        \
    for (int ks = 0; ks < 2; ks++) {                                         \
        const int k2w = ks * 8 + tig;                                        \
        unsigned ah[4][4], al[4][4], bh[4][2], bl[4][2];                     \
        _Pragma("unroll")                                                    \
        for (int mt = 0; mt < 4; mt++) {                                     \
            const unsigned* _ph = (APH);                                     \
            const unsigned* _pl = (APL);                                     \
            ah[mt][0] = _ph[0];            al[mt][0] = _pl[0];               \
            ah[mt][1] = _ph[(AOR)];        al[mt][1] = _pl[(AOR)];           \
            ah[mt][2] = _ph[(AOK)];        al[mt][2] = _pl[(AOK)];           \
            ah[mt][3] = _ph[(AOR)+(AOK)];  al[mt][3] = _pl[(AOR)+(AOK)];     \
        }                                                                    \
        _Pragma("unroll")                                                    \
        for (int nt = 0; nt < 4; nt++) {                                     \
            const unsigned* _qh = (BPH);                                     \
            const unsigned* _ql = (BPL);                                     \
            bh[nt][0] = _qh[0];  bh[nt][1] = _qh[(BOK)];                     \
            bl[nt][0] = _ql[0];  bl[nt][1] = _ql[(BOK)];                     \
        }                                                                    \
        _Pragma("unroll")                                                    \
        for (int nt = 0; nt < 4; nt++)                                       \
            _Pragma("unroll")                                                \
            for (int mt = 0; mt < 4; mt++)                                   \
                mma_f16(acc[mt][nt], al[mt], bh[nt]);                        \
        _Pragma("unroll")                                                    \
        for (int nt = 0; nt < 4; nt++)                                       \
            _Pragma("unroll")                                                \
            for (int mt = 0; mt < 4; mt++)                                   \
                mma_f16(acc[mt][nt], ah[mt], bl[nt]);                        \
        _Pragma("unroll")                                                    \
        for (int nt = 0; nt < 4; nt++)                                       \
            _Pragma("unroll")                                                \
            for (int mt = 0; mt < 4; mt++)                                   \
                mma_f16(acc[mt][nt], ah[mt], bh[nt]);                        \
    }

#define ZERO_ACC()                                                            \
    float acc[4][4][4];                                                       \
    _Pragma("unroll")                                                         \
    for (int a = 0; a < 4; a++)                                               \
        _Pragma("unroll")                                                     \
        for (int b = 0; b < 4; b++)                                           \
            _Pragma("unroll")                                                 \
            for (int c = 0; c < 4; c++) acc[a][b][c] = 0.f;

// ============================================================================
// Prep 1: x [256 c][32768 p] -> packed planes [128 c2][32768 p]
// ============================================================================
__global__ void __launch_bounds__(256) prep_x(const float* __restrict__ x)
{
    int idx = blockIdx.x * 256 + threadIdx.x;
    int c2 = idx >> 13;               // 0..127
    int p4 = (idx & 8191) << 2;       // 0..32764
    float4 r0 = *(const float4*)&x[(size_t)(2 * c2)     * NP + p4];
    float4 r1 = *(const float4*)&x[(size_t)(2 * c2 + 1) * NP + p4];
    unsigned h0,l0,h1,l1,h2,l2,h3,l3;
    split_pack(r0.x, r1.x, h0, l0); split_pack(r0.y, r1.y, h1, l1);
    split_pack(r0.z, r1.z, h2, l2); split_pack(r0.w, r1.w, h3, l3);
    *(uint4*)&g_xh[(size_t)c2 * NP + p4] = make_uint4(h0, h1, h2, h3);
    *(uint4*)&g_xl[(size_t)c2 * NP + p4] = make_uint4(l0, l1, l2, l3);
}

// ============================================================================
// Prep 2: weights -> packed planes. qkv: [1536][128 c2]; wo: [512][256 c2].
// ============================================================================
__global__ void __launch_bounds__(256) prep_w(
    const float* __restrict__ wq,
    const float* __restrict__ wkv,
    const float* __restrict__ wo)
{
    int idx = blockIdx.x * 256 + threadIdx.x;
    if (idx < 49152) {                       // 1536 rows x 32 segs (8 c each)
        int row = idx >> 5, sg = idx & 31;
        const float* arow = (row < 512) ? (wq + row * 256) : (wkv + (row - 512) * 256);
        float4 a = *(const float4*)&arow[sg * 8];
        float4 b = *(const float4*)&arow[sg * 8 + 4];
        unsigned h0,l0,h1,l1,h2,l2,h3,l3;
        split_pack(a.x, a.y, h0, l0); split_pack(a.z, a.w, h1, l1);
        split_pack(b.x, b.y, h2, l2); split_pack(b.z, b.w, h3, l3);
        *(uint4*)&g_wh[row * 128 + sg * 4] = make_uint4(h0, h1, h2, h3);
        *(uint4*)&g_wl[row * 128 + sg * 4] = make_uint4(l0, l1, l2, l3);
    } else if (idx < 49152 + 32768) {        // wo: 512 rows x 64 segs
        int j = idx - 49152;
        int row = j >> 6, sg = j & 63;
        float4 a = *(const float4*)&wo[row * 512 + sg * 8];
        float4 b = *(const float4*)&wo[row * 512 + sg * 8 + 4];
        unsigned h0,l0,h1,l1,h2,l2,h3,l3;
        split_pack(a.x, a.y, h0, l0); split_pack(a.z, a.w, h1, l1);
        split_pack(b.x, b.y, h2, l2); split_pack(b.z, b.w, h3, l3);
        *(uint4*)&g_woh[row * 256 + sg * 4] = make_uint4(h0, h1, h2, h3);
        *(uint4*)&g_wol[row * 256 + sg * 4] = make_uint4(l0, l1, l2, l3);
    }
}

// ============================================================================
// Kernel 1: QKV projection, pure cp.async + MMA, 2-stage pipeline.
// Block 128p(M) x 128o(N), 8 k-chunks of 32 c.
// Stage: XsH[16*136] XsL[16*136] WsH[128*20] WsL[128*20] = 9472 words.
// ============================================================================
#define PJ_STG 9472
__global__ void __launch_bounds__(256) proj_kernel()
{
    extern __shared__ __align__(16) unsigned sj[];

    const int tid  = threadIdx.x;
    const int lane = tid & 31, warp = tid >> 5;
    const int g = lane >> 2, tig = lane & 3;
    const int wm = (warp >> 2) * 64;       // p
    const int wn = (warp & 3) * 32;        // o
    const int p0 = blockIdx.x * 128;
    const int o0 = blockIdx.y * 128;

    ZERO_ACC();

    auto issue = [&](int kt, int buf) {
        unsigned* b   = sj + buf * PJ_STG;
        unsigned* xsH = b;
        unsigned* xsL = b + 2176;
        unsigned* wsH = b + 4352;
        unsigned* wsL = b + 6912;
        #pragma unroll
        for (int q = 0; q < 4; q++) {          // X: 1024 x 16B
            int cid = q * 256 + tid;
            int pl = cid >> 9, row = (cid >> 5) & 15, seg = cid & 31;
            const unsigned* src = (pl ? g_xl : g_xh) +
                (size_t)(kt * 16 + row) * NP + p0 + seg * 4;
            cpa16(s2u((pl ? xsL : xsH) + row * 136 + seg * 4), src);
        }
        #pragma unroll
        for (int q = 0; q < 4; q++) {          // W: 1024 x 16B
            int cid = q * 256 + tid;
            int pl = cid >> 9, row = (cid >> 2) & 127, seg = cid & 3;
            const unsigned* src = (pl ? g_wl : g_wh) +
                (size_t)(o0 + row) * 128 + kt * 16 + seg * 4;
            cpa16(s2u((pl ? wsL : wsH) + row * 20 + seg * 4), src);
        }
    };

    issue(0, 0);
    CP_COMMIT;
    for (int kt = 0; kt < 8; kt++) {
        if (kt + 1 < 8) issue(kt + 1, (kt + 1) & 1);
        CP_COMMIT;
        CP_WAIT(1);
        __syncthreads();
        unsigned* b   = sj + (kt & 1) * PJ_STG;
        unsigned* xsH = b;
        unsigned* xsL = b + 2176;
        unsigned* wsH = b + 4352;
        unsigned* wsL = b + 6912;
        MMAH_K32(&xsH[k2w * 136 + wm + mt * 16 + g],
                 &xsL[k2w * 136 + wm + mt * 16 + g], 8, 544,
                 &wsH[(wn + nt * 8 + g) * 20 + k2w],
                 &wsL[(wn + nt * 8 + g) * 20 + k2w], 4);
        __syncthreads();
    }

    // epilogue: write Q/K/V packed hi/lo planes; Q pre-scaled by 0.125
    #pragma unroll
    for (int nt = 0; nt < 4; nt++) {
        int o   = o0 + wn + nt * 8 + 2 * tig;
        int sel = o >> 9;
        int oc  = o & 511;
        int gd = (oc >> 6) * 64;
        int dl = oc & 63;
        #pragma unroll
        for (int mt = 0; mt < 4; mt++) {
            #pragma unroll
            for (int r = 0; r < 2; r++) {
                int p  = p0 + wm + mt * 16 + g + r * 8;
                int f  = p >> 14, hh = (p >> 7) & 127, ww = p & 127;
                int gidx = gd + (hh >> 4) * 8 + (ww >> 4);
                int i    = f * 256 + (hh & 15) * 16 + (ww & 15);
                float a = acc[mt][nt][r * 2], bq = acc[mt][nt][r * 2 + 1];
                if (sel == 0) {
                    unsigned hi, lo;
                    split_pack(a * 0.125f, bq * 0.125f, hi, lo);
                    int off = (gidx * 512 + i) * 32 + (dl >> 1);
                    g_qh[off] = hi; g_ql[off] = lo;
                } else if (sel == 1) {
                    unsigned hi, lo;
                    split_pack(a, bq, hi, lo);
                    int off = (gidx * 512 + i) * 32 + (dl >> 1);
                    g_kh[off] = hi; g_kl[off] = lo;
                } else {
                    float pa = __shfl_xor_sync(0xffffffffu, a, 4);
                    float pb = __shfl_xor_sync(0xffffffffu, bq, 4);
                    if (!(g & 1)) {
                        unsigned h0, l0, h1, l1;
                        split_pack(a, pa, h0, l0);
                        split_pack(bq, pb, h1, l1);
                        int off = (gidx * 256 + (i >> 1)) * 64 + dl;
                        *(uint2*)&g_vh[off] = make_uint2(h0, h1);
                        *(uint2*)&g_vl[off] = make_uint2(l0, l1);
                    }
                }
            }
        }
    }
}

// ============================================================================
// Kernel 2: fused flash attention (round-9, unchanged).
// ============================================================================
#define FA_STG 9216
__global__ void __launch_bounds__(128, 3) attn_kernel()
{
    extern __shared__ __align__(16) unsigned sf[];

    const int tid  = threadIdx.x;
    const int lane = tid & 31, wid = tid >> 5;
    const int g = lane >> 2, tig = lane & 3;
    const int gz = blockIdx.y;
    const int i0 = blockIdx.x * 64;

    unsigned qah[4][4], qal[4][4];
    {
        const size_t qrow = (size_t)(gz * 512 + i0 + wid * 16 + g) * 32;
        #pragma unroll
        for (int ks = 0; ks < 4; ks++) {
            int w = ks * 8 + tig;
            qah[ks][0] = g_qh[qrow + w];
            qah[ks][1] = g_qh[qrow + 256 + w];
            qah[ks][2] = g_qh[qrow + w + 4];
            qah[ks][3] = g_qh[qrow + 256 + w + 4];
            qal[ks][0] = g_ql[qrow + w];
            qal[ks][1] = g_ql[qrow + 256 + w];
            qal[ks][2] = g_ql[qrow + w + 4];
            qal[ks][3] = g_ql[qrow + 256 + w + 4];
        }
    }

    float acc_o[8][4];
    #pragma unroll
    for (int a = 0; a < 8; a++)
        #pragma unroll
        for (int b = 0; b < 4; b++) acc_o[a][b] = 0.f;
    float m0 = -1e30f, m1 = -1e30f, l0 = 0.f, l1 = 0.f;

    auto issue = [&](int jt, int buf) {
        unsigned* b = sf + buf * FA_STG;
        #pragma unroll
        for (int q = 0; q < 8; q++) {
            int cid = q * 128 + tid;
            int pl = cid >> 9, row = (cid >> 3) & 63, seg = cid & 7;
            const unsigned* src = (pl ? g_kl : g_kh) +
                (size_t)(gz * 512 + jt * 64 + row) * 32 + seg * 4;
            cpa16(s2u(b + pl * 2304 + row * 36 + seg * 4), src);
        }
        #pragma unroll
        for (int q = 0; q < 8; q++) {
            int cid = q * 128 + tid;
            int pl = cid >> 9, r = (cid >> 4) & 31, seg = cid & 15;
            const unsigned* src = (pl ? g_vl : g_vh) +
                (size_t)(gz * 256 + jt * 32 + r) * 64 + seg * 4;
            cpa16(s2u(b + 4608 + pl * 2304 + r * 72 + seg * 4), src);
        }
    };

    issue(0, 0);
    CP_COMMIT;
    for (int jt = 0; jt < 8; jt++) {
        if (jt + 1 < 8) issue(jt + 1, (jt + 1) & 1);
        CP_COMMIT;
        CP_WAIT(1);
        __syncthreads();
        unsigned* b  = sf + (jt & 1) * FA_STG;
        unsigned* KH = b;
        unsigned* KL = b + 2304;
        unsigned* VH = b + 4608;
        unsigned* VL = b + 6912;

        float sacc[8][4];
        #pragma unroll
        for (int a = 0; a < 8; a++)
            #pragma unroll
            for (int c = 0; c < 4; c++) sacc[a][c] = 0.f;

        #pragma unroll
        for (int ks = 0; ks < 4; ks++) {
            #pragma unroll
            for (int h = 0; h < 2; h++) {
                unsigned bh[4][2], bl[4][2];
                #pragma unroll
                for (int q = 0; q < 4; q++) {
                    int nt = h * 4 + q;
                    const unsigned* ph = &KH[(nt * 8 + g) * 36 + ks * 8 + tig];
                    const unsigned* pl = &KL[(nt * 8 + g) * 36 + ks * 8 + tig];
                    bh[q][0] = ph[0]; bh[q][1] = ph[4];
                    bl[q][0] = pl[0]; bl[q][1] = pl[4];
                }
                #pragma unroll
                for (int q = 0; q < 4; q++) mma_f16(sacc[h * 4 + q], qal[ks], bh[q]);
                #pragma unroll
                for (int q = 0; q < 4; q++) mma_f16(sacc[h * 4 + q], qah[ks], bl[q]);
                #pragma unroll
                for (int q = 0; q < 4; q++) mma_f16(sacc[h * 4 + q], qah[ks], bh[q]);
            }
        }

        float mx0 = -1e30f, mx1 = -1e30f;
        #pragma unroll
        for (int nt = 0; nt < 8; nt++) {
            mx0 = fmaxf(mx0, fmaxf(sacc[nt][0], sacc[nt][1]));
            mx1 = fmaxf(mx1, fmaxf(sacc[nt][2], sacc[nt][3]));
        }
        mx0 = fmaxf(mx0, __shfl_xor_sync(0xffffffffu, mx0, 1));
        mx0 = fmaxf(mx0, __shfl_xor_sync(0xffffffffu, mx0, 2));
        mx1 = fmaxf(mx1, __shfl_xor_sync(0xffffffffu, mx1, 1));
        mx1 = fmaxf(mx1, __shfl_xor_sync(0xffffffffu, mx1, 2));
        float mn0 = fmaxf(m0, mx0), mn1 = fmaxf(m1, mx1);
        float c0 = __expf(m0 - mn0), c1 = __expf(m1 - mn1);
        m0 = mn0; m1 = mn1;
        float s0 = 0.f, s1 = 0.f;
        #pragma unroll
        for (int nt = 0; nt < 8; nt++) {
            sacc[nt][0] = __expf(sacc[nt][0] - mn0);
            sacc[nt][1] = __expf(sacc[nt][1] - mn0);
            sacc[nt][2] = __expf(sacc[nt][2] - mn1);
            sacc[nt][3] = __expf(sacc[nt][3] - mn1);
            s0 += sacc[nt][0] + sacc[nt][1];
            s1 += sacc[nt][2] + sacc[nt][3];
        }
        s0 += __shfl_xor_sync(0xffffffffu, s0, 1);
        s0 += __shfl_xor_sync(0xffffffffu, s0, 2);
        s1 += __shfl_xor_sync(0xffffffffu, s1, 1);
        s1 += __shfl_xor_sync(0xffffffffu, s1, 2);
        l0 = l0 * c0 + s0;
        l1 = l1 * c1 + s1;
        #pragma unroll
        for (int nt = 0; nt < 8; nt++) {
            acc_o[nt][0] *= c0; acc_o[nt][1] *= c0;
            acc_o[nt][2] *= c1; acc_o[nt][3] *= c1;
        }

        #pragma unroll
        for (int kt = 0; kt < 4; kt++) {
            unsigned pah[4], pal[4];
            split_pack(sacc[2 * kt][0],     sacc[2 * kt][1],     pah[0], pal[0]);
            split_pack(sacc[2 * kt][2],     sacc[2 * kt][3],     pah[1], pal[1]);
            split_pack(sacc[2 * kt + 1][0], sacc[2 * kt + 1][1], pah[2], pal[2]);
            split_pack(sacc[2 * kt + 1][2], sacc[2 * kt + 1][3], pah[3], pal[3]);
            #pragma unroll
            for (int h = 0; h < 2; h++) {
                unsigned bh[4][2], bl[4][2];
                #pragma unroll
                for (int q = 0; q < 4; q++) {
                    int nt = h * 4 + q;
                    const unsigned* ph = &VH[(kt * 8 + tig) * 72 + nt * 8 + g];
                    const unsigned* pl = &VL[(kt * 8 + tig) * 72 + nt * 8 + g];
                    bh[q][0] = ph[0]; bh[q][1] = ph[288];
                    bl[q][0] = pl[0]; bl[q][1] = pl[288];
                }
                #pragma unroll
                for (int q = 0; q < 4; q++) mma_f16(acc_o[h * 4 + q], pal, bh[q]);
                #pragma unroll
                for (int q = 0; q < 4; q++) mma_f16(acc_o[h * 4 + q], pah, bl[q]);
                #pragma unroll
                for (int q = 0; q < 4; q++) mma_f16(acc_o[h * 4 + q], pah, bh[q]);
            }
        }
        __syncthreads();
    }

    float rl0 = __fdividef(1.0f, l0), rl1 = __fdividef(1.0f, l1);
    int ia = i0 + wid * 16 + g;
    float* row0 = &g_ow[(gz * 512 + ia) * 64];
    float* row1 = &g_ow[(gz * 512 + ia + 8) * 64];
    #pragma unroll
    for (int nt = 0; nt < 8; nt++) {
        int d = nt * 8 + 2 * tig;
        *(float2*)&row0[d] = make_float2(acc_o[nt][0] * rl0, acc_o[nt][1] * rl0);
        *(float2*)&row1[d] = make_float2(acc_o[nt][2] * rl1, acc_o[nt][3] * rl1);
    }
}

// ============================================================================
// Kernel 3: window layout [g][i][d] -> packed pixel planes [c2][p].
// ============================================================================
__global__ void __launch_bounds__(256) transpose_kernel()
{
    __shared__ __align__(16) float T[128][68];

    const int tid = threadIdx.x;
    const int g  = blockIdx.y;
    const int i0 = blockIdx.x * 128;
    const float* src = g_ow + (g * 512 + i0) * 64;

    #pragma unroll
    for (int q = 0; q < 8; q++) {
        int idx = q * 256 + tid;       // 0..2047
        int row = idx >> 4;            // 0..127
        int d4  = (idx & 15) * 4;
        *(float4*)&T[row][d4] = *(const float4*)&src[row * 64 + d4];
    }
    __syncthreads();

    const int head = g >> 6;
    const int win  = g & 63;
    const int wxv  = win >> 3, wyv = win & 7;

    // 256 threads = 32 d-pairs x 8 runs; each thread: 16 p words per plane
    {
        int d2  = tid & 31;            // d-pair 0..31
        int run = tid >> 5;            // 0..7
        int d   = d2 * 2;
        int ib  = run * 16;
        int ig  = i0 + ib;
        int f   = ig >> 8;
        int w1  = (ig >> 4) & 15;
        int pbase = f * 16384 + (wxv * 16 + w1) * 128 + wyv * 16;
        unsigned* dh = g_oph + (size_t)(head * 32 + d2) * NP + pbase;
        unsigned* dl = g_opl + (size_t)(head * 32 + d2) * NP + pbase;
        #pragma unroll
        for (int e = 0; e < 4; e++) {
            unsigned h[4], l[4];
            #pragma unroll
            for (int k = 0; k < 4; k++) {
                int r = ib + e * 4 + k;
                split_pack(T[r][d], T[r][d + 1], h[k], l[k]);
            }
            *(uint4*)&dh[e * 4] = make_uint4(h[0], h[1], h[2], h[3]);
            *(uint4*)&dl[e * 4] = make_uint4(l[0], l[1], l[2], l[3]);
        }
    }
}

// ============================================================================
// Kernel 4: final projection + bias, pure cp.async + MMA, 2-stage pipeline.
// Block 128o(M) x 128p(N), 16 k-chunks of 32 c.
// Stage: BsH[16*136] BsL[16*136] WsH[128*20] WsL[128*20] = 9472 words.
// ============================================================================
__global__ void __launch_bounds__(256) out_kernel(
    const float* __restrict__ bo,
    float* __restrict__ out)
{
    extern __shared__ __align__(16) unsigned so[];

    const int tid  = threadIdx.x;
    const int lane = tid & 31, warp = tid >> 5;
    const int g = lane >> 2, tig = lane & 3;
    const int wm = (warp >> 2) * 64;       // o
    const int wn = (warp & 3) * 32;        // p
    const int p0 = blockIdx.x * 128;
    const int o0 = blockIdx.y * 128;

    ZERO_ACC();

    auto issue = [&](int kt, int buf) {
        unsigned* b   = so + buf * PJ_STG;
        unsigned* bsH = b;
        unsigned* bsL = b + 2176;
        unsigned* wsH = b + 4352;
        unsigned* wsL = b + 6912;
        #pragma unroll
        for (int q = 0; q < 4; q++) {          // data: 1024 x 16B
            int cid = q * 256 + tid;
            int pl = cid >> 9, row = (cid >> 5) & 15, seg = cid & 31;
            const unsigned* src = (pl ? g_opl : g_oph) +
                (size_t)(kt * 16 + row) * NP + p0 + seg * 4;
            cpa16(s2u((pl ? bsL : bsH) + row * 136 + seg * 4), src);
        }
        #pragma unroll
        for (int q = 0; q < 4; q++) {          // wo: 1024 x 16B
            int cid = q * 256 + tid;
            int pl = cid >> 9, row = (cid >> 2) & 127, seg = cid & 3;
            const unsigned* src = (pl ? g_wol : g_woh) +
                (size_t)(o0 + row) * 256 + kt * 16 + seg * 4;
            cpa16(s2u((pl ? wsL : wsH) + row * 20 + seg * 4), src);
        }
    };

    issue(0, 0);
    CP_COMMIT;
    for (int kt = 0; kt < 16; kt++) {
        if (kt + 1 < 16) issue(kt + 1, (kt + 1) & 1);
        CP_COMMIT;
        CP_WAIT(1);
        __syncthreads();
        unsigned* b   = so + (kt & 1) * PJ_STG;
        unsigned* bsH = b;
        unsigned* bsL = b + 2176;
        unsigned* wsH = b + 4352;
        unsigned* wsL = b + 6912;
        MMAH_K32(&wsH[(wm + mt * 16 + g) * 20 + k2w],
                 &wsL[(wm + mt * 16 + g) * 20 + k2w], 160, 4,
                 &bsH[k2w * 136 + wn + nt * 8 + g],
                 &bsL[k2w * 136 + wn + nt * 8 + g], 544);
        __syncthreads();
    }

    #pragma unroll
    for (int mt = 0; mt < 4; mt++) {
        int o  = o0 + wm + mt * 16 + g;
        float b0 = bo[o];
        float b1 = bo[o + 8];
        #pragma unroll
        for (int nt = 0; nt < 4; nt++) {
            int p = p0 + wn + nt * 8 + 2 * tig;
            *(float2*)&out[o * NP + p] =
                make_float2(acc[mt][nt][0] + b0, acc[mt][nt][1] + b0);
            *(float2*)&out[(o + 8) * NP + p] =
                make_float2(acc[mt][nt][2] + b1, acc[mt][nt][3] + b1);
        }
    }
}

// ============================================================================
extern "C" void kernel_launch(void* const* d_in, const int* in_sizes, int n_in,
                              void* d_out, int out_size)
{
    const float* x   = (const float*)d_in[0];
    const float* wq  = (const float*)d_in[1];
    const float* wkv = (const float*)d_in[2];
    const float* wo  = (const float*)d_in[3];
    const float* bo  = (const float*)d_in[4];
    float* out = (float*)d_out;

    const int PJ_SMEM = 2 * PJ_STG * 4;        // 75776 B
    const int FA_SMEM = 2 * FA_STG * 4;        // 73728 B

    static int attr_done = 0;
    if (!attr_done) {
        cudaFuncSetAttribute(proj_kernel, cudaFuncAttributeMaxDynamicSharedMemorySize, PJ_SMEM);
        cudaFuncSetAttribute(attn_kernel, cudaFuncAttributeMaxDynamicSharedMemorySize, FA_SMEM);
        cudaFuncSetAttribute(out_kernel,  cudaFuncAttributeMaxDynamicSharedMemorySize, PJ_SMEM);
        attr_done = 1;
    }

    prep_x          <<<4096, 256>>>(x);
    prep_w          <<<320, 256>>>(wq, wkv, wo);
    proj_kernel     <<<dim3(NP / 128, 1536 / 128), 256, PJ_SMEM>>>();
    attn_kernel     <<<dim3(8, NG),                128, FA_SMEM>>>();
    transpose_kernel<<<dim3(4, NG),                256>>>();
    out_kernel      <<<dim3(NP / 128, 256 / 128),  256, PJ_SMEM>>>(bo, out);
}